// round 13
// baseline (speedup 1.0000x reference)
#include <cuda_runtime.h>
#include <cuda_fp16.h>
#include <cstdint>

#define VOCAB 50257
#define EMBED 512
#define HID   1024
#define G4    4096
#define NCLS  10
#define B_    64
#define S_    512
#define BS_   (B_*S_)
#define NCTA  128

// ---------------- device scratch (no allocations allowed) ----------------
__device__ __half  g_E16[(size_t)BS_*EMBED];    // gathered embeddings, row r = t*64+b
__device__ __half  g_Wx16[(size_t)G4*EMBED];    // Wg[:, :512] fp16
__device__ __half  g_Wh16[(size_t)G4*HID];      // Wg[:, 512:] fp16, scan-permuted rows
__device__ __half  g_Wa16[(size_t)HID*HID];
__device__ __half  g_Xc [(size_t)BS_*G4];       // x-part of gates (+bg), blocked cols
__device__ __half  g_hs [(size_t)BS_*HID];      // all hidden states, row r = t*64+b
__device__ float   g_energy[BS_];
__device__ float   g_ctx[B_*HID];
__device__ unsigned g_barc[256];                // [2 groups][4 chunks] x 32-word padding

// ---------------- helpers ----------------
__device__ __forceinline__ void ldmx4(unsigned r[4], const void* p) {
    unsigned a = (unsigned)__cvta_generic_to_shared(p);
    asm volatile("ldmatrix.sync.aligned.m8n8.x4.shared.b16 {%0,%1,%2,%3}, [%4];"
        : "=r"(r[0]), "=r"(r[1]), "=r"(r[2]), "=r"(r[3]) : "r"(a));
}
__device__ __forceinline__ void mma16816(float* c, const unsigned* a, const unsigned* b) {
    asm volatile("mma.sync.aligned.m16n8k16.row.col.f32.f16.f16.f32 "
        "{%0,%1,%2,%3},{%4,%5,%6,%7},{%8,%9},{%0,%1,%2,%3};"
        : "+f"(c[0]), "+f"(c[1]), "+f"(c[2]), "+f"(c[3])
        : "r"(a[0]), "r"(a[1]), "r"(a[2]), "r"(a[3]), "r"(b[0]), "r"(b[1]));
}
__device__ __forceinline__ unsigned ld_acq(const unsigned* p) {
    unsigned v;
    asm volatile("ld.acquire.gpu.global.u32 %0, [%1];" : "=r"(v) : "l"(p) : "memory");
    return v;
}
__device__ __forceinline__ void red_rel_add(unsigned* p, unsigned v) {
    asm volatile("red.release.gpu.global.add.u32 [%0], %1;" :: "l"(p), "r"(v) : "memory");
}
__device__ __forceinline__ void cp16(void* dst, const void* src) {
    unsigned d = (unsigned)__cvta_generic_to_shared(dst);
    asm volatile("cp.async.cg.shared.global [%0], [%1], 16;" :: "r"(d), "l"(src));
}
__device__ __forceinline__ float fsig(float x) { return __fdividef(1.f, 1.f + __expf(-x)); }
__device__ __forceinline__ float ftanh(float x) { return 2.f * fsig(2.f * x) - 1.f; }

// ---------------- K0: reset per-launch state ----------------
__global__ void reset_kernel() {
    int i = blockIdx.x * blockDim.x + threadIdx.x;
    if (i < 256) g_barc[i] = 0u;
    if (i < BS_) g_energy[i] = 0.f;
}

// ---------------- K1: fp32 -> fp16 weight conversions ----------------
__global__ void convert_kernel(const float* __restrict__ Wg, const float* __restrict__ Wa) {
    size_t i0 = (size_t)blockIdx.x * blockDim.x + threadIdx.x;
    size_t stride = (size_t)gridDim.x * blockDim.x;
    for (size_t i = i0; i < (size_t)G4 * EMBED; i += stride) {
        int n = (int)(i >> 9), k = (int)(i & 511);
        g_Wx16[i] = __float2half_rn(Wg[(size_t)n * 1536 + k]);
    }
    // scan layout: row = hc*64 + p, p = d_local*4 + q  <->  original n = q*1024 + hc*16 + d_local
    for (size_t i = i0; i < (size_t)G4 * HID; i += stride) {
        int pos = (int)(i >> 10), k = (int)(i & 1023);
        int hc = pos >> 6, p = pos & 63;
        int n = ((p & 3) << 10) + (hc << 4) + (p >> 2);
        g_Wh16[i] = __float2half_rn(Wg[(size_t)n * 1536 + 512 + k]);
    }
    for (size_t i = i0; i < (size_t)HID * HID; i += stride)
        g_Wa16[i] = __float2half_rn(Wa[i]);
}

// ---------------- K2: gather embeddings to fp16, row = t*64+b ----------------
__global__ void gather_kernel(const int* __restrict__ x, const float* __restrict__ emb) {
    size_t i = (size_t)blockIdx.x * blockDim.x + threadIdx.x;   // over BS_*256 half2
    if (i >= (size_t)BS_ * 256) return;
    int r = (int)(i >> 8), k2 = (int)(i & 255);
    int b = r & 63, t = r >> 6;
    int tok = x[b * 512 + t];
    float2 v = ((const float2*)emb)[(size_t)tok * 256 + k2];
    ((half2*)g_E16)[i] = __floats2half2_rn(v.x, v.y);
}

// ---------------- K3: Xc GEMM v4 — A-tile resident, 8 warps of 64x32 tiles ----------------
// grid (4 bq, 256 bm). A-tile (128 x 512, 133KB) loaded once; loops 8 strips of 128 cols,
// streaming B in 128-K chunks through a 2x34KB double buffer. Warp grid 2(m) x 4(n),
// 64x32 tiles: 0.094 B/MAC LDSM -> crossbar below the HMMA floor.
#define ASTRIDE 520
#define BSTRIDE 136
#define BBUF    (128 * BSTRIDE)
__global__ __launch_bounds__(256, 1) void xc_kernel(const float* __restrict__ aux) {
    extern __shared__ __half xs[];
    __half* Asm = xs;                       // 128 x 520
    __half* Bsm = xs + 128 * ASTRIDE;       // 2 x 128 x 136

    int tid = threadIdx.x;
    int warp = tid >> 5, lane = tid & 31;
    int wm = warp >> 2, wn = warp & 3;      // 2x4 warp grid, 64x32 tiles over 128x128
    int grp = lane >> 2, c0 = (lane & 3) * 2;
    int bq = blockIdx.x, bm = blockIdx.y;

    // load A tile: 128 rows x 512 halfs (8192 16B chunks, 32 per thread)
    #pragma unroll
    for (int i = 0; i < 32; i++) {
        int idx = tid + i * 256;
        int r = idx >> 6, s = idx & 63;
        cp16(&Asm[r * ASTRIDE + s * 8], &g_E16[(size_t)(bm * 128 + r) * 512 + s * 8]);
    }
    asm volatile("cp.async.commit_group;");

    auto loadB = [&](int j, int st) {       // j in [0,32): strip (j>>2), K-chunk (j&3)
        int str = j >> 2, c = j & 3;
        #pragma unroll
        for (int i = 0; i < 8; i++) {
            int idx = tid + i * 256;        // 2048 chunks: 128 rows x 16
            int r = idx >> 4, s = idx & 15;
            cp16(&Bsm[st * BBUF + r * BSTRIDE + s * 8],
                 &g_Wx16[(size_t)(bq * 1024 + str * 128 + r) * 512 + c * 128 + s * 8]);
        }
        asm volatile("cp.async.commit_group;");
    };

    float acc[4][4][4];
    #pragma unroll
    for (int a = 0; a < 4; a++)
        #pragma unroll
        for (int b = 0; b < 4; b++)
            #pragma unroll
            for (int c = 0; c < 4; c++) acc[a][b][c] = 0.f;

    loadB(0, 0);
    #pragma unroll 1
    for (int j = 0; j < 32; j++) {
        int c = j & 3;
        if (j < 31) {
            loadB(j + 1, (j + 1) & 1);
            asm volatile("cp.async.wait_group 1;");   // A + chunk j done, j+1 in flight
        } else {
            asm volatile("cp.async.wait_group 0;");
        }
        __syncthreads();
        const __half* bs = &Bsm[(j & 1) * BBUF];
        #pragma unroll
        for (int kk = 0; kk < 128; kk += 16) {
            unsigned af[4][4];
            #pragma unroll
            for (int mf = 0; mf < 4; mf++)
                ldmx4(af[mf], &Asm[(wm * 64 + mf * 16 + (lane & 15)) * ASTRIDE
                                   + c * 128 + kk + ((lane >> 4) << 3)]);
            unsigned bf[4][2];
            #pragma unroll
            for (int hb = 0; hb < 2; hb++) {
                unsigned r[4];
                int n = wn * 32 + hb * 16 + ((lane >> 4) << 3) + (lane & 7);
                int kq = kk + (((lane >> 3) & 1) << 3);
                ldmx4(r, &bs[n * BSTRIDE + kq]);
                bf[hb * 2 + 0][0] = r[0]; bf[hb * 2 + 0][1] = r[1];
                bf[hb * 2 + 1][0] = r[2]; bf[hb * 2 + 1][1] = r[3];
            }
            #pragma unroll
            for (int mf = 0; mf < 4; mf++)
                #pragma unroll
                for (int nf = 0; nf < 4; nf++)
                    mma16816(acc[mf][nf], af[mf], bf[nf]);
        }

        if (c == 3) {                       // finished K for this strip: epilogue + reset
            int str = j >> 2;
            #pragma unroll
            for (int mf = 0; mf < 4; mf++)
                #pragma unroll
                for (int rp = 0; rp < 2; rp++) {
                    int rg = bm * 128 + wm * 64 + mf * 16 + grp + rp * 8;
                    #pragma unroll
                    for (int nf = 0; nf < 4; nf++) {
                        int n0 = bq * 1024 + str * 128 + wn * 32 + nf * 8 + c0;
                        float v0 = acc[mf][nf][rp * 2 + 0] + aux[n0];
                        float v1 = acc[mf][nf][rp * 2 + 1] + aux[n0 + 1];
                        int q = n0 >> 10, d = n0 & 1023;
                        int p = ((d >> 3) << 5) + (q << 3) + (d & 7);
                        *(half2*)&g_Xc[(size_t)rg * G4 + p] = __floats2half2_rn(v0, v1);
                    }
                }
            #pragma unroll
            for (int a = 0; a < 4; a++)
                #pragma unroll
                for (int b = 0; b < 4; b++)
                    #pragma unroll
                    for (int cc = 0; cc < 4; cc++) acc[a][b][cc] = 0.f;
        }
        __syncthreads();                    // buffer j&1 reads done before issue(j+2)
    }
}

// ---------------- K5: energy GEMM v2 — B-tile resident, A streamed ----------------
// grid (16 bn, 16 bmg). B strip (64 n-rows x 1024 K, 132KB) resident; loops 16 bm tiles
// (128 rows), streaming A in 128-K chunks through a 2x34KB double buffer.
// T = hs @ Wa16^T; sum_n tanh(T)*va[n] -> atomicAdd g_energy[row].
#define EBSTRIDE 1032
__global__ __launch_bounds__(256, 1) void energy_kernel(const float* __restrict__ aux) {
    extern __shared__ __half es[];
    __half* Bsm = es;                       // 64 x 1032 (resident)
    __half* Asm = es + 64 * EBSTRIDE;       // 2 x 128 x 136

    int tid = threadIdx.x;
    int warp = tid >> 5, lane = tid & 31;
    int wm = warp & 3, wn = warp >> 2;      // 4x2 warp grid, 32x32 tiles
    int grp = lane >> 2, c0 = (lane & 3) * 2;
    int bn = blockIdx.x, bmg = blockIdx.y;

    // load B strip: 64 rows x 1024 halfs (8192 16B chunks, 32 per thread)
    #pragma unroll
    for (int i = 0; i < 32; i++) {
        int idx = tid + i * 256;
        int r = idx >> 7, s = idx & 127;
        cp16(&Bsm[r * EBSTRIDE + s * 8], &g_Wa16[(size_t)(bn * 64 + r) * 1024 + s * 8]);
    }
    asm volatile("cp.async.commit_group;");

    auto loadA = [&](int j, int st) {       // j in [0,128): bm tile (j>>3), K-chunk (j&7)
        int bm = bmg * 16 + (j >> 3), c = j & 7;
        #pragma unroll
        for (int i = 0; i < 8; i++) {
            int idx = tid + i * 256;        // 2048 chunks: 128 rows x 16
            int r = idx >> 4, s = idx & 15;
            cp16(&Asm[st * BBUF + r * BSTRIDE + s * 8],
                 &g_hs[(size_t)(bm * 128 + r) * 1024 + c * 128 + s * 8]);
        }
        asm volatile("cp.async.commit_group;");
    };

    float acc[2][4][4];
    #pragma unroll
    for (int a = 0; a < 2; a++)
        #pragma unroll
        for (int b = 0; b < 4; b++)
            #pragma unroll
            for (int c = 0; c < 4; c++) acc[a][b][c] = 0.f;

    loadA(0, 0);
    #pragma unroll 1
    for (int j = 0; j < 128; j++) {
        int c = j & 7;
        if (j < 127) {
            loadA(j + 1, (j + 1) & 1);
            asm volatile("cp.async.wait_group 1;");   // B + chunk j done, j+1 in flight
        } else {
            asm volatile("cp.async.wait_group 0;");
        }
        __syncthreads();
        const __half* as = &Asm[(j & 1) * BBUF];
        #pragma unroll
        for (int kk = 0; kk < 128; kk += 16) {
            unsigned af[2][4];
            #pragma unroll
            for (int mf = 0; mf < 2; mf++)
                ldmx4(af[mf], &as[(wm * 32 + mf * 16 + (lane & 15)) * BSTRIDE
                                  + kk + ((lane >> 4) << 3)]);
            unsigned bf[4][2];
            #pragma unroll
            for (int hb = 0; hb < 2; hb++) {
                unsigned r[4];
                int n = wn * 32 + hb * 16 + ((lane >> 4) << 3) + (lane & 7);
                int kq = c * 128 + kk + (((lane >> 3) & 1) << 3);
                ldmx4(r, &Bsm[n * EBSTRIDE + kq]);
                bf[hb * 2 + 0][0] = r[0]; bf[hb * 2 + 0][1] = r[1];
                bf[hb * 2 + 1][0] = r[2]; bf[hb * 2 + 1][1] = r[3];
            }
            #pragma unroll
            for (int mf = 0; mf < 2; mf++)
                #pragma unroll
                for (int nf = 0; nf < 4; nf++)
                    mma16816(acc[mf][nf], af[mf], bf[nf]);
        }

        if (c == 7) {                       // finished K for this bm tile: epilogue + reset
            int bm = bmg * 16 + (j >> 3);
            #pragma unroll
            for (int mf = 0; mf < 2; mf++)
                #pragma unroll
                for (int rp = 0; rp < 2; rp++) {
                    int rg = bm * 128 + wm * 32 + mf * 16 + grp + rp * 8;
                    float s = 0.f;
                    #pragma unroll
                    for (int nf = 0; nf < 4; nf++)
                        #pragma unroll
                        for (int cc = 0; cc < 2; cc++) {
                            int n = bn * 64 + wn * 32 + nf * 8 + c0 + cc;
                            s += ftanh(acc[mf][nf][rp * 2 + cc]) * aux[n];
                        }
                    s += __shfl_xor_sync(0xffffffffu, s, 1);
                    s += __shfl_xor_sync(0xffffffffu, s, 2);
                    if ((lane & 3) == 0) atomicAdd(&g_energy[rg], s);
                }
            #pragma unroll
            for (int a = 0; a < 2; a++)
                #pragma unroll
                for (int b = 0; b < 4; b++)
                    #pragma unroll
                    for (int cc = 0; cc < 4; cc++) acc[a][b][cc] = 0.f;
        }
        __syncthreads();                    // buffer j&1 reads done before issue(j+2)
    }
}

// ---------------- K4: persistent LSTM scan v6 — per-K-chunk barriers ----------------
// CTA (bg,hc): batch rows [bg*32,+32), dims [hc*16,+16) -> 64 gate cols (p = d*4+q).
// 8 warps: (wk) K-chunk of 256, (wn) 32 gate cols. Weight fragments in registers.
// Chunk wk of h_{t-1} is produced by the 16 CTAs with hc>>4==wk -> warp-pair wk waits
// ONLY on barrier slot (bg,wk): max-of-16 skew, chunks pipeline independently.
__global__ __launch_bounds__(256, 1) void scan_kernel() {
    extern __shared__ __half sh[];
    __half* Wsm = sh;                              // 64 x 1032 (dead after preload)
    __half* Hsm = sh + 64 * 1032;                  // 32 x 1032
    float*  Psf = (float*)sh;                      // alias into Wsm: [4][32][68] fp32
    int tid = threadIdx.x, cta = blockIdx.x;
    int w = tid >> 5, lane = tid & 31;
    int wk = w >> 1, wn = w & 1;
    int grp = lane >> 2, c0 = (lane & 3) * 2;
    int bg = cta >> 6, hc = cta & 63;
    int kbase = wk * 256;
    int lt = tid & 63;                             // lane within warp pair
    unsigned* wait_slot = &g_barc[(bg * 4 + wk) * 32];          // consumer side
    unsigned* arr_slot  = &g_barc[(bg * 4 + (hc >> 4)) * 32];   // producer side

    // stage weights: rows hc*64 .. hc*64+64 of scan-permuted Wh
    for (int i = tid; i < 64 * 128; i += 256) {
        int r = i >> 7, s = i & 127;
        *(uint4*)&Wsm[r * 1032 + s * 8] =
            *(const uint4*)&g_Wh16[((size_t)hc * 64 + r) * 1024 + s * 8];
    }
    __syncthreads();

    // preload this warp's weight fragments for its whole 256-K chunk into registers
    unsigned bfr[16][4][2];
    {
        int n = wn * 32 + ((lane >> 4) << 3) + (lane & 7);
        #pragma unroll
        for (int it = 0; it < 16; it++) {
            int kq = kbase + it * 16 + (((lane >> 3) & 1) << 3);
            unsigned r[4];
            ldmx4(r, &Wsm[n * 1032 + kq]);
            bfr[it][0][0] = r[0]; bfr[it][0][1] = r[1];
            bfr[it][1][0] = r[2]; bfr[it][1][1] = r[3];
            ldmx4(r, &Wsm[(n + 16) * 1032 + kq]);
            bfr[it][2][0] = r[0]; bfr[it][2][1] = r[1];
            bfr[it][3][0] = r[2]; bfr[it][3][1] = r[3];
        }
    }
    __syncthreads();   // Wsm reads complete before Psf (alias) is ever written

    int m = tid >> 3, e0 = (tid & 7) * 2;          // epilogue ownership: row m, dims e0,e0+1
    int rowg = bg * 32 + m;
    int xbase = (((hc * 16 + e0) >> 3) << 5) + (e0 & 7);   // blocked Xc addressing
    float cc0 = 0.f, cc1 = 0.f;

    for (int t = 0; t < S_; t++) {
        // prefetch x-part of gates (independent of h_{t-1})
        const __half* xrow = &g_Xc[((size_t)t * 64 + rowg) * G4 + xbase];
        half2 hx0 = *(const half2*)&xrow[0];
        half2 hx1 = *(const half2*)&xrow[8];
        half2 hx2 = *(const half2*)&xrow[16];
        half2 hx3 = *(const half2*)&xrow[24];

        float acc[2][4][4];
        #pragma unroll
        for (int a = 0; a < 2; a++)
            #pragma unroll
            for (int b = 0; b < 4; b++)
                #pragma unroll
                for (int c = 0; c < 4; c++) acc[a][b][c] = 0.f;

        if (t > 0) {
            // per-chunk wait: one lane polls, pair barrier propagates (acquire chains)
            if (lt == 0) {
                unsigned target = 16u * (unsigned)t;
                while (ld_acq(wait_slot) < target) {}
            }
            asm volatile("bar.sync %0, 64;" :: "r"(1 + wk));

            // warp pair stages 32 rows x 256 K in TWO 8KB halves (overlap load 2 w/ mma 1)
            const __half* hp = &g_hs[((size_t)(t - 1) * 64 + bg * 32) * 1024];
            #pragma unroll
            for (int i = 0; i < 8; i++) {
                int idx = lt + i * 64;             // 0..511: 32 rows x 16 chunks
                int r = idx >> 4, s = idx & 15;
                cp16(&Hsm[r * 1032 + kbase + s * 8], &hp[r * 1024 + kbase + s * 8]);
            }
            asm volatile("cp.async.commit_group;");
            #pragma unroll
            for (int i = 0; i < 8; i++) {
                int idx = lt + i * 64;
                int r = idx >> 4, s = idx & 15;
                cp16(&Hsm[r * 1032 + kbase + 128 + s * 8], &hp[r * 1024 + kbase + 128 + s * 8]);
            }
            asm volatile("cp.async.commit_group;");

            #pragma unroll
            for (int half = 0; half < 2; half++) {
                if (half == 0) asm volatile("cp.async.wait_group 1;");
                else           asm volatile("cp.async.wait_group 0;");
                asm volatile("bar.sync %0, 64;" :: "r"(1 + wk));
                #pragma unroll
                for (int it = half * 8; it < half * 8 + 8; it++) {
                    int kk = kbase + it * 16;
                    unsigned af[2][4];
                    #pragma unroll
                    for (int mf = 0; mf < 2; mf++)
                        ldmx4(af[mf], &Hsm[(mf * 16 + (lane & 15)) * 1032 + kk + ((lane >> 4) << 3)]);
                    #pragma unroll
                    for (int mf = 0; mf < 2; mf++)
                        #pragma unroll
                        for (int nf = 0; nf < 4; nf++)
                            mma16816(acc[mf][nf], af[mf], bfr[it][nf]);
                }
            }
        }

        // Psum write (aliases Wsm, NOT Hsm; prev-step Psf reads finished at loop-end sync)
        #pragma unroll
        for (int mf = 0; mf < 2; mf++)
            #pragma unroll
            for (int nf = 0; nf < 4; nf++)
                #pragma unroll
                for (int rp = 0; rp < 2; rp++) {
                    int mm = mf * 16 + grp + rp * 8;
                    *(float2*)&Psf[(wk * 32 + mm) * 68 + wn * 32 + nf * 8 + c0] =
                        make_float2(acc[mf][nf][rp * 2 + 0], acc[mf][nf][rp * 2 + 1]);
                }
        __syncthreads();

        // cell update: this thread owns (row m, dims e0,e0+1); Psum cols p = e*4+q
        float4 sa = make_float4(0.f, 0.f, 0.f, 0.f);
        float4 sb = make_float4(0.f, 0.f, 0.f, 0.f);
        #pragma unroll
        for (int k = 0; k < 4; k++) {
            float4 va = *(const float4*)&Psf[(k * 32 + m) * 68 + e0 * 4];
            float4 vb = *(const float4*)&Psf[(k * 32 + m) * 68 + e0 * 4 + 4];
            sa.x += va.x; sa.y += va.y; sa.z += va.z; sa.w += va.w;
            sb.x += vb.x; sb.y += vb.y; sb.z += vb.z; sb.w += vb.w;
        }
        float h0, h1;
        {
            float iv = fsig (sa.x + __low2float(hx0));
            float fv = fsig (sa.y + __low2float(hx1));
            float gv = ftanh(sa.z + __low2float(hx2));
            float ov = fsig (sa.w + __low2float(hx3));
            cc0 = fv * cc0 + iv * gv;
            h0 = ov * ftanh(cc0);
        }
        {
            float iv = fsig (sb.x + __high2float(hx0));
            float fv = fsig (sb.y + __high2float(hx1));
            float gv = ftanh(sb.z + __high2float(hx2));
            float ov = fsig (sb.w + __high2float(hx3));
            cc1 = fv * cc1 + iv * gv;
            h1 = ov * ftanh(cc1);
        }
        *(half2*)&g_hs[((size_t)t * 64 + rowg) * 1024 + hc * 16 + e0] =
            __floats2half2_rn(h0, h1);

        __syncthreads();                 // all h STG + Psf reads done before release
        if (tid == 0) red_rel_add(arr_slot, 1u);
    }
}

// ---------------- K6: masked softmax + context, grid (8 dim-chunks, 64 batch) ----------------
__global__ void attn_kernel(const int* __restrict__ x) {
    __shared__ float sa[512];
    __shared__ float red[256];
    int chunk = blockIdx.x, b = blockIdx.y, tid = threadIdx.x;

    float ea = g_energy[tid * 64 + b];
    float eb = g_energy[(tid + 256) * 64 + b];
    if (x[b * 512 + tid] == 0)       ea = -1e10f;
    if (x[b * 512 + tid + 256] == 0) eb = -1e10f;
    red[tid] = fmaxf(ea, eb); __syncthreads();
    for (int s = 128; s > 0; s >>= 1) {
        if (tid < s) red[tid] = fmaxf(red[tid], red[tid + s]);
        __syncthreads();
    }
    float mx = red[0]; __syncthreads();
    float xa = __expf(ea - mx), xb = __expf(eb - mx);
    red[tid] = xa + xb; __syncthreads();
    for (int s = 128; s > 0; s >>= 1) {
        if (tid < s) red[tid] += red[tid + s];
        __syncthreads();
    }
    float inv = __fdividef(1.f, red[0]);
    sa[tid] = xa * inv;
    sa[tid + 256] = xb * inv;
    __syncthreads();

    int d = chunk * 128 + (tid & 127);
    int th = tid >> 7;
    const __half* hp = &g_hs[(size_t)b * 1024 + d];
    float s0 = 0.f, s1 = 0.f;
    #pragma unroll 4
    for (int t = th * 256; t < th * 256 + 256; t += 2) {
        s0 += sa[t]     * __half2float(hp[(size_t)t       * 64 * 1024]);
        s1 += sa[t + 1] * __half2float(hp[(size_t)(t + 1) * 64 * 1024]);
    }
    red[tid] = s0 + s1;
    __syncthreads();
    if (tid < 128) g_ctx[b * HID + d] = red[tid] + red[tid + 128];
}

// ---------------- K7: final classifier (fp32) ----------------
__global__ void final_kernel(const float* __restrict__ WV, const float* __restrict__ bV,
                             float* __restrict__ out) {
    int i = blockIdx.x * blockDim.x + threadIdx.x;
    if (i >= B_ * NCLS) return;
    int b = i / NCLS, n = i % NCLS;
    const float* c = &g_ctx[b * HID];
    const float* w = &WV[n * HID];
    float s = bV[n];
    #pragma unroll 8
    for (int k = 0; k < HID; k++) s += c[k] * w[k];
    out[i] = s;
}

// ---------------- launch ----------------
extern "C" void kernel_launch(void* const* d_in, const int* in_sizes, int n_in,
                              void* d_out, int out_size) {
    const int*   x   = (const int*)  d_in[0];
    const float* emb = (const float*)d_in[1];
    const float* Wg  = (const float*)d_in[2];
    const float* bg  = (const float*)d_in[3];
    const float* Wa  = (const float*)d_in[4];
    const float* va  = (const float*)d_in[5];
    const float* WV  = (const float*)d_in[6];
    const float* bV  = (const float*)d_in[7];
    float* out = (float*)d_out;
    (void)n_in; (void)in_sizes; (void)out_size;

    reset_kernel<<<128, 256>>>();
    convert_kernel<<<2048, 256>>>(Wg, Wa);
    gather_kernel<<<BS_, 256>>>(x, emb);

    const int smem_xc = (128 * ASTRIDE + 2 * BBUF) * (int)sizeof(__half);  // 202752
    cudaFuncSetAttribute(xc_kernel, cudaFuncAttributeMaxDynamicSharedMemorySize, smem_xc);
    xc_kernel<<<dim3(4, 256), 256, smem_xc>>>(bg);

    const int smem_scan = (64 * 1032 + 32 * 1032) * (int)sizeof(__half);   // 198144
    cudaFuncSetAttribute(scan_kernel, cudaFuncAttributeMaxDynamicSharedMemorySize, smem_scan);
    scan_kernel<<<NCTA, 256, smem_scan>>>();

    const int smem_en = (64 * EBSTRIDE + 2 * BBUF) * (int)sizeof(__half);  // 201728
    cudaFuncSetAttribute(energy_kernel, cudaFuncAttributeMaxDynamicSharedMemorySize, smem_en);
    energy_kernel<<<dim3(16, 16), 256, smem_en>>>(va);

    attn_kernel<<<dim3(8, 64), 256>>>(x);
    final_kernel<<<3, 256>>>(WV, bV, out);
}

// round 14
// speedup vs baseline: 1.0433x; 1.0433x over previous
#include <cuda_runtime.h>
#include <cuda_fp16.h>
#include <cstdint>

#define VOCAB 50257
#define EMBED 512
#define HID   1024
#define G4    4096
#define NCLS  10
#define B_    64
#define S_    512
#define BS_   (B_*S_)
#define NCTA  128

// ---------------- device scratch (no allocations allowed) ----------------
__device__ __half  g_E16[(size_t)BS_*EMBED];    // gathered embeddings, row r = t*64+b
__device__ __half  g_Wx16[(size_t)G4*EMBED];    // Wg[:, :512] fp16
__device__ __half  g_Wh16[(size_t)G4*HID];      // Wg[:, 512:] fp16, scan-permuted rows
__device__ __half  g_Wa16[(size_t)HID*HID];
__device__ __half  g_Xc [(size_t)BS_*G4];       // x-part of gates (+bg), blocked cols
__device__ __half  g_hs [(size_t)BS_*HID];      // all hidden states, row r = t*64+b
__device__ float   g_energy[BS_];
__device__ float   g_ctx[B_*HID];
__device__ unsigned g_barc[256];                // [2 groups][4 chunks] x 32-word padding

// ---------------- helpers ----------------
__device__ __forceinline__ void ldmx4(unsigned r[4], const void* p) {
    unsigned a = (unsigned)__cvta_generic_to_shared(p);
    asm volatile("ldmatrix.sync.aligned.m8n8.x4.shared.b16 {%0,%1,%2,%3}, [%4];"
        : "=r"(r[0]), "=r"(r[1]), "=r"(r[2]), "=r"(r[3]) : "r"(a));
}
__device__ __forceinline__ void mma16816(float* c, const unsigned* a, const unsigned* b) {
    asm volatile("mma.sync.aligned.m16n8k16.row.col.f32.f16.f16.f32 "
        "{%0,%1,%2,%3},{%4,%5,%6,%7},{%8,%9},{%0,%1,%2,%3};"
        : "+f"(c[0]), "+f"(c[1]), "+f"(c[2]), "+f"(c[3])
        : "r"(a[0]), "r"(a[1]), "r"(a[2]), "r"(a[3]), "r"(b[0]), "r"(b[1]));
}
__device__ __forceinline__ unsigned ld_acq(const unsigned* p) {
    unsigned v;
    asm volatile("ld.acquire.gpu.global.u32 %0, [%1];" : "=r"(v) : "l"(p) : "memory");
    return v;
}
__device__ __forceinline__ void red_rel_add(unsigned* p, unsigned v) {
    asm volatile("red.release.gpu.global.add.u32 [%0], %1;" :: "l"(p), "r"(v) : "memory");
}
__device__ __forceinline__ void cp16(void* dst, const void* src) {
    unsigned d = (unsigned)__cvta_generic_to_shared(dst);
    asm volatile("cp.async.cg.shared.global [%0], [%1], 16;" :: "r"(d), "l"(src));
}
__device__ __forceinline__ float fsig(float x) { return __fdividef(1.f, 1.f + __expf(-x)); }
__device__ __forceinline__ float ftanh(float x) { return 2.f * fsig(2.f * x) - 1.f; }

// ---------------- K0: reset per-launch state ----------------
__global__ void reset_kernel() {
    int i = blockIdx.x * blockDim.x + threadIdx.x;
    if (i < 256) g_barc[i] = 0u;
    if (i < BS_) g_energy[i] = 0.f;
}

// ---------------- K1: fp32 -> fp16 weight conversions ----------------
__global__ void convert_kernel(const float* __restrict__ Wg, const float* __restrict__ Wa) {
    size_t i0 = (size_t)blockIdx.x * blockDim.x + threadIdx.x;
    size_t stride = (size_t)gridDim.x * blockDim.x;
    for (size_t i = i0; i < (size_t)G4 * EMBED; i += stride) {
        int n = (int)(i >> 9), k = (int)(i & 511);
        g_Wx16[i] = __float2half_rn(Wg[(size_t)n * 1536 + k]);
    }
    // scan layout: row = hc*64 + p, p = d_local*4 + q  <->  original n = q*1024 + hc*16 + d_local
    for (size_t i = i0; i < (size_t)G4 * HID; i += stride) {
        int pos = (int)(i >> 10), k = (int)(i & 1023);
        int hc = pos >> 6, p = pos & 63;
        int n = ((p & 3) << 10) + (hc << 4) + (p >> 2);
        g_Wh16[i] = __float2half_rn(Wg[(size_t)n * 1536 + 512 + k]);
    }
    for (size_t i = i0; i < (size_t)HID * HID; i += stride)
        g_Wa16[i] = __float2half_rn(Wa[i]);
}

// ---------------- K2: gather embeddings to fp16, row = t*64+b ----------------
__global__ void gather_kernel(const int* __restrict__ x, const float* __restrict__ emb) {
    size_t i = (size_t)blockIdx.x * blockDim.x + threadIdx.x;   // over BS_*256 half2
    if (i >= (size_t)BS_ * 256) return;
    int r = (int)(i >> 8), k2 = (int)(i & 255);
    int b = r & 63, t = r >> 6;
    int tok = x[b * 512 + t];
    float2 v = ((const float2*)emb)[(size_t)tok * 256 + k2];
    ((half2*)g_E16)[i] = __floats2half2_rn(v.x, v.y);
}

// ---------------- K3: Xc GEMM v4 — A-tile resident, 8 warps of 64x32 tiles ----------------
// grid (4 bq, 256 bm). A-tile (128 x 512, 133KB) loaded once; loops 8 strips of 128 cols,
// streaming B in 128-K chunks through a 2x34KB double buffer. Warp grid 2(m) x 4(n),
// 64x32 tiles: 0.094 B/MAC LDSM -> crossbar below the HMMA floor.
#define ASTRIDE 520
#define BSTRIDE 136
#define BBUF    (128 * BSTRIDE)
__global__ __launch_bounds__(256, 1) void xc_kernel(const float* __restrict__ aux) {
    extern __shared__ __half xs[];
    __half* Asm = xs;                       // 128 x 520
    __half* Bsm = xs + 128 * ASTRIDE;       // 2 x 128 x 136

    int tid = threadIdx.x;
    int warp = tid >> 5, lane = tid & 31;
    int wm = warp >> 2, wn = warp & 3;      // 2x4 warp grid, 64x32 tiles over 128x128
    int grp = lane >> 2, c0 = (lane & 3) * 2;
    int bq = blockIdx.x, bm = blockIdx.y;

    // load A tile: 128 rows x 512 halfs (8192 16B chunks, 32 per thread)
    #pragma unroll
    for (int i = 0; i < 32; i++) {
        int idx = tid + i * 256;
        int r = idx >> 6, s = idx & 63;
        cp16(&Asm[r * ASTRIDE + s * 8], &g_E16[(size_t)(bm * 128 + r) * 512 + s * 8]);
    }
    asm volatile("cp.async.commit_group;");

    auto loadB = [&](int j, int st) {       // j in [0,32): strip (j>>2), K-chunk (j&3)
        int str = j >> 2, c = j & 3;
        #pragma unroll
        for (int i = 0; i < 8; i++) {
            int idx = tid + i * 256;        // 2048 chunks: 128 rows x 16
            int r = idx >> 4, s = idx & 15;
            cp16(&Bsm[st * BBUF + r * BSTRIDE + s * 8],
                 &g_Wx16[(size_t)(bq * 1024 + str * 128 + r) * 512 + c * 128 + s * 8]);
        }
        asm volatile("cp.async.commit_group;");
    };

    float acc[4][4][4];
    #pragma unroll
    for (int a = 0; a < 4; a++)
        #pragma unroll
        for (int b = 0; b < 4; b++)
            #pragma unroll
            for (int c = 0; c < 4; c++) acc[a][b][c] = 0.f;

    loadB(0, 0);
    #pragma unroll 1
    for (int j = 0; j < 32; j++) {
        int c = j & 3;
        if (j < 31) {
            loadB(j + 1, (j + 1) & 1);
            asm volatile("cp.async.wait_group 1;");   // A + chunk j done, j+1 in flight
        } else {
            asm volatile("cp.async.wait_group 0;");
        }
        __syncthreads();
        const __half* bs = &Bsm[(j & 1) * BBUF];
        #pragma unroll
        for (int kk = 0; kk < 128; kk += 16) {
            unsigned af[4][4];
            #pragma unroll
            for (int mf = 0; mf < 4; mf++)
                ldmx4(af[mf], &Asm[(wm * 64 + mf * 16 + (lane & 15)) * ASTRIDE
                                   + c * 128 + kk + ((lane >> 4) << 3)]);
            unsigned bf[4][2];
            #pragma unroll
            for (int hb = 0; hb < 2; hb++) {
                unsigned r[4];
                int n = wn * 32 + hb * 16 + ((lane >> 4) << 3) + (lane & 7);
                int kq = kk + (((lane >> 3) & 1) << 3);
                ldmx4(r, &bs[n * BSTRIDE + kq]);
                bf[hb * 2 + 0][0] = r[0]; bf[hb * 2 + 0][1] = r[1];
                bf[hb * 2 + 1][0] = r[2]; bf[hb * 2 + 1][1] = r[3];
            }
            #pragma unroll
            for (int mf = 0; mf < 4; mf++)
                #pragma unroll
                for (int nf = 0; nf < 4; nf++)
                    mma16816(acc[mf][nf], af[mf], bf[nf]);
        }

        if (c == 3) {                       // finished K for this strip: epilogue + reset
            int str = j >> 2;
            #pragma unroll
            for (int mf = 0; mf < 4; mf++)
                #pragma unroll
                for (int rp = 0; rp < 2; rp++) {
                    int rg = bm * 128 + wm * 64 + mf * 16 + grp + rp * 8;
                    #pragma unroll
                    for (int nf = 0; nf < 4; nf++) {
                        int n0 = bq * 1024 + str * 128 + wn * 32 + nf * 8 + c0;
                        float v0 = acc[mf][nf][rp * 2 + 0] + aux[n0];
                        float v1 = acc[mf][nf][rp * 2 + 1] + aux[n0 + 1];
                        int q = n0 >> 10, d = n0 & 1023;
                        int p = ((d >> 3) << 5) + (q << 3) + (d & 7);
                        *(half2*)&g_Xc[(size_t)rg * G4 + p] = __floats2half2_rn(v0, v1);
                    }
                }
            #pragma unroll
            for (int a = 0; a < 4; a++)
                #pragma unroll
                for (int b = 0; b < 4; b++)
                    #pragma unroll
                    for (int cc = 0; cc < 4; cc++) acc[a][b][cc] = 0.f;
        }
        __syncthreads();                    // buffer j&1 reads done before issue(j+2)
    }
}

// ---------------- K5: energy GEMM v2 — B-tile resident, A streamed ----------------
// grid (16 bn, 16 bmg). B strip (64 n-rows x 1024 K, 132KB) resident; loops 16 bm tiles
// (128 rows), streaming A in 128-K chunks through a 2x34KB double buffer.
// T = hs @ Wa16^T; sum_n tanh(T)*va[n] -> atomicAdd g_energy[row].
#define EBSTRIDE 1032
__global__ __launch_bounds__(256, 1) void energy_kernel(const float* __restrict__ aux) {
    extern __shared__ __half es[];
    __half* Bsm = es;                       // 64 x 1032 (resident)
    __half* Asm = es + 64 * EBSTRIDE;       // 2 x 128 x 136

    int tid = threadIdx.x;
    int warp = tid >> 5, lane = tid & 31;
    int wm = warp & 3, wn = warp >> 2;      // 4x2 warp grid, 32x32 tiles
    int grp = lane >> 2, c0 = (lane & 3) * 2;
    int bn = blockIdx.x, bmg = blockIdx.y;

    // load B strip: 64 rows x 1024 halfs (8192 16B chunks, 32 per thread)
    #pragma unroll
    for (int i = 0; i < 32; i++) {
        int idx = tid + i * 256;
        int r = idx >> 7, s = idx & 127;
        cp16(&Bsm[r * EBSTRIDE + s * 8], &g_Wa16[(size_t)(bn * 64 + r) * 1024 + s * 8]);
    }
    asm volatile("cp.async.commit_group;");

    auto loadA = [&](int j, int st) {       // j in [0,128): bm tile (j>>3), K-chunk (j&7)
        int bm = bmg * 16 + (j >> 3), c = j & 7;
        #pragma unroll
        for (int i = 0; i < 8; i++) {
            int idx = tid + i * 256;        // 2048 chunks: 128 rows x 16
            int r = idx >> 4, s = idx & 15;
            cp16(&Asm[st * BBUF + r * BSTRIDE + s * 8],
                 &g_hs[(size_t)(bm * 128 + r) * 1024 + c * 128 + s * 8]);
        }
        asm volatile("cp.async.commit_group;");
    };

    float acc[2][4][4];
    #pragma unroll
    for (int a = 0; a < 2; a++)
        #pragma unroll
        for (int b = 0; b < 4; b++)
            #pragma unroll
            for (int c = 0; c < 4; c++) acc[a][b][c] = 0.f;

    loadA(0, 0);
    #pragma unroll 1
    for (int j = 0; j < 128; j++) {
        int c = j & 7;
        if (j < 127) {
            loadA(j + 1, (j + 1) & 1);
            asm volatile("cp.async.wait_group 1;");   // B + chunk j done, j+1 in flight
        } else {
            asm volatile("cp.async.wait_group 0;");
        }
        __syncthreads();
        const __half* as = &Asm[(j & 1) * BBUF];
        #pragma unroll
        for (int kk = 0; kk < 128; kk += 16) {
            unsigned af[2][4];
            #pragma unroll
            for (int mf = 0; mf < 2; mf++)
                ldmx4(af[mf], &as[(wm * 32 + mf * 16 + (lane & 15)) * BSTRIDE
                                  + kk + ((lane >> 4) << 3)]);
            unsigned bf[4][2];
            #pragma unroll
            for (int hb = 0; hb < 2; hb++) {
                unsigned r[4];
                int n = wn * 32 + hb * 16 + ((lane >> 4) << 3) + (lane & 7);
                int kq = c * 128 + kk + (((lane >> 3) & 1) << 3);
                ldmx4(r, &Bsm[n * EBSTRIDE + kq]);
                bf[hb * 2 + 0][0] = r[0]; bf[hb * 2 + 0][1] = r[1];
                bf[hb * 2 + 1][0] = r[2]; bf[hb * 2 + 1][1] = r[3];
            }
            #pragma unroll
            for (int mf = 0; mf < 2; mf++)
                #pragma unroll
                for (int nf = 0; nf < 4; nf++)
                    mma16816(acc[mf][nf], af[mf], bf[nf]);
        }

        if (c == 7) {                       // finished K for this bm tile: epilogue + reset
            int bm = bmg * 16 + (j >> 3);
            #pragma unroll
            for (int mf = 0; mf < 2; mf++)
                #pragma unroll
                for (int rp = 0; rp < 2; rp++) {
                    int rg = bm * 128 + wm * 32 + mf * 16 + grp + rp * 8;
                    float s = 0.f;
                    #pragma unroll
                    for (int nf = 0; nf < 4; nf++)
                        #pragma unroll
                        for (int cc = 0; cc < 2; cc++) {
                            int n = bn * 64 + wn * 32 + nf * 8 + c0 + cc;
                            s += ftanh(acc[mf][nf][rp * 2 + cc]) * aux[n];
                        }
                    s += __shfl_xor_sync(0xffffffffu, s, 1);
                    s += __shfl_xor_sync(0xffffffffu, s, 2);
                    if ((lane & 3) == 0) atomicAdd(&g_energy[rg], s);
                }
            #pragma unroll
            for (int a = 0; a < 2; a++)
                #pragma unroll
                for (int b = 0; b < 4; b++)
                    #pragma unroll
                    for (int cc = 0; cc < 4; cc++) acc[a][b][cc] = 0.f;
        }
        __syncthreads();                    // buffer j&1 reads done before issue(j+2)
    }
}

// ---------------- K4: persistent LSTM scan v6.1 — per-K-chunk barriers, all-lane poll ----------------
// CTA (bg,hc): batch rows [bg*32,+32), dims [hc*16,+16) -> 64 gate cols (p = d*4+q).
// 8 warps: (wk) K-chunk of 256, (wn) 32 gate cols. Weight fragments in registers.
// Chunk wk of h_{t-1} is produced by the 16 CTAs with hc>>4==wk -> warp-pair wk waits
// ONLY on barrier slot (bg,wk). ALL 64 lanes poll (own acquire orders own cp.async) —
// no detect->propagate barrier.
__global__ __launch_bounds__(256, 1) void scan_kernel() {
    extern __shared__ __half sh[];
    __half* Wsm = sh;                              // 64 x 1032 (dead after preload)
    __half* Hsm = sh + 64 * 1032;                  // 32 x 1032
    float*  Psf = (float*)sh;                      // alias into Wsm: [4][32][68] fp32
    int tid = threadIdx.x, cta = blockIdx.x;
    int w = tid >> 5, lane = tid & 31;
    int wk = w >> 1, wn = w & 1;
    int grp = lane >> 2, c0 = (lane & 3) * 2;
    int bg = cta >> 6, hc = cta & 63;
    int kbase = wk * 256;
    int lt = tid & 63;                             // lane within warp pair
    unsigned* wait_slot = &g_barc[(bg * 4 + wk) * 32];          // consumer side
    unsigned* arr_slot  = &g_barc[(bg * 4 + (hc >> 4)) * 32];   // producer side

    // stage weights: rows hc*64 .. hc*64+64 of scan-permuted Wh
    for (int i = tid; i < 64 * 128; i += 256) {
        int r = i >> 7, s = i & 127;
        *(uint4*)&Wsm[r * 1032 + s * 8] =
            *(const uint4*)&g_Wh16[((size_t)hc * 64 + r) * 1024 + s * 8];
    }
    __syncthreads();

    // preload this warp's weight fragments for its whole 256-K chunk into registers
    unsigned bfr[16][4][2];
    {
        int n = wn * 32 + ((lane >> 4) << 3) + (lane & 7);
        #pragma unroll
        for (int it = 0; it < 16; it++) {
            int kq = kbase + it * 16 + (((lane >> 3) & 1) << 3);
            unsigned r[4];
            ldmx4(r, &Wsm[n * 1032 + kq]);
            bfr[it][0][0] = r[0]; bfr[it][0][1] = r[1];
            bfr[it][1][0] = r[2]; bfr[it][1][1] = r[3];
            ldmx4(r, &Wsm[(n + 16) * 1032 + kq]);
            bfr[it][2][0] = r[0]; bfr[it][2][1] = r[1];
            bfr[it][3][0] = r[2]; bfr[it][3][1] = r[3];
        }
    }
    __syncthreads();   // Wsm reads complete before Psf (alias) is ever written

    int m = tid >> 3, e0 = (tid & 7) * 2;          // epilogue ownership: row m, dims e0,e0+1
    int rowg = bg * 32 + m;
    int xbase = (((hc * 16 + e0) >> 3) << 5) + (e0 & 7);   // blocked Xc addressing
    float cc0 = 0.f, cc1 = 0.f;

    for (int t = 0; t < S_; t++) {
        // prefetch x-part of gates (independent of h_{t-1})
        const __half* xrow = &g_Xc[((size_t)t * 64 + rowg) * G4 + xbase];
        half2 hx0 = *(const half2*)&xrow[0];
        half2 hx1 = *(const half2*)&xrow[8];
        half2 hx2 = *(const half2*)&xrow[16];
        half2 hx3 = *(const half2*)&xrow[24];

        float acc[2][4][4];
        #pragma unroll
        for (int a = 0; a < 2; a++)
            #pragma unroll
            for (int b = 0; b < 4; b++)
                #pragma unroll
                for (int c = 0; c < 4; c++) acc[a][b][c] = 0.f;

        if (t > 0) {
            // per-chunk wait: EVERY lane polls; its own acquire orders its own cp.async
            {
                unsigned target = 16u * (unsigned)t;
                while (ld_acq(wait_slot) < target) {}
            }

            // warp pair stages 32 rows x 256 K in TWO 8KB halves (overlap load 2 w/ mma 1)
            const __half* hp = &g_hs[((size_t)(t - 1) * 64 + bg * 32) * 1024];
            #pragma unroll
            for (int i = 0; i < 8; i++) {
                int idx = lt + i * 64;             // 0..511: 32 rows x 16 chunks
                int r = idx >> 4, s = idx & 15;
                cp16(&Hsm[r * 1032 + kbase + s * 8], &hp[r * 1024 + kbase + s * 8]);
            }
            asm volatile("cp.async.commit_group;");
            #pragma unroll
            for (int i = 0; i < 8; i++) {
                int idx = lt + i * 64;
                int r = idx >> 4, s = idx & 15;
                cp16(&Hsm[r * 1032 + kbase + 128 + s * 8], &hp[r * 1024 + kbase + 128 + s * 8]);
            }
            asm volatile("cp.async.commit_group;");

            #pragma unroll
            for (int half = 0; half < 2; half++) {
                if (half == 0) asm volatile("cp.async.wait_group 1;");
                else           asm volatile("cp.async.wait_group 0;");
                asm volatile("bar.sync %0, 64;" :: "r"(1 + wk));
                #pragma unroll
                for (int it = half * 8; it < half * 8 + 8; it++) {
                    int kk = kbase + it * 16;
                    unsigned af[2][4];
                    #pragma unroll
                    for (int mf = 0; mf < 2; mf++)
                        ldmx4(af[mf], &Hsm[(mf * 16 + (lane & 15)) * 1032 + kk + ((lane >> 4) << 3)]);
                    #pragma unroll
                    for (int mf = 0; mf < 2; mf++)
                        #pragma unroll
                        for (int nf = 0; nf < 4; nf++)
                            mma16816(acc[mf][nf], af[mf], bfr[it][nf]);
                }
            }
        }

        // Psum write (aliases Wsm, NOT Hsm; prev-step Psf reads finished at loop-end sync)
        #pragma unroll
        for (int mf = 0; mf < 2; mf++)
            #pragma unroll
            for (int nf = 0; nf < 4; nf++)
                #pragma unroll
                for (int rp = 0; rp < 2; rp++) {
                    int mm = mf * 16 + grp + rp * 8;
                    *(float2*)&Psf[(wk * 32 + mm) * 68 + wn * 32 + nf * 8 + c0] =
                        make_float2(acc[mf][nf][rp * 2 + 0], acc[mf][nf][rp * 2 + 1]);
                }
        __syncthreads();

        // cell update: this thread owns (row m, dims e0,e0+1); Psum cols p = e*4+q
        float4 sa = make_float4(0.f, 0.f, 0.f, 0.f);
        float4 sb = make_float4(0.f, 0.f, 0.f, 0.f);
        #pragma unroll
        for (int k = 0; k < 4; k++) {
            float4 va = *(const float4*)&Psf[(k * 32 + m) * 68 + e0 * 4];
            float4 vb = *(const float4*)&Psf[(k * 32 + m) * 68 + e0 * 4 + 4];
            sa.x += va.x; sa.y += va.y; sa.z += va.z; sa.w += va.w;
            sb.x += vb.x; sb.y += vb.y; sb.z += vb.z; sb.w += vb.w;
        }
        float h0, h1;
        {
            float iv = fsig (sa.x + __low2float(hx0));
            float fv = fsig (sa.y + __low2float(hx1));
            float gv = ftanh(sa.z + __low2float(hx2));
            float ov = fsig (sa.w + __low2float(hx3));
            cc0 = fv * cc0 + iv * gv;
            h0 = ov * ftanh(cc0);
        }
        {
            float iv = fsig (sb.x + __high2float(hx0));
            float fv = fsig (sb.y + __high2float(hx1));
            float gv = ftanh(sb.z + __high2float(hx2));
            float ov = fsig (sb.w + __high2float(hx3));
            cc1 = fv * cc1 + iv * gv;
            h1 = ov * ftanh(cc1);
        }
        *(half2*)&g_hs[((size_t)t * 64 + rowg) * 1024 + hc * 16 + e0] =
            __floats2half2_rn(h0, h1);

        __syncthreads();                 // all h STG + Psf reads done before release
        if (tid == 0) red_rel_add(arr_slot, 1u);
    }
}

// ---------------- K6: masked softmax + context, grid (8 dim-chunks, 64 batch) ----------------
__global__ void attn_kernel(const int* __restrict__ x) {
    __shared__ float sa[512];
    __shared__ float red[256];
    int chunk = blockIdx.x, b = blockIdx.y, tid = threadIdx.x;

    float ea = g_energy[tid * 64 + b];
    float eb = g_energy[(tid + 256) * 64 + b];
    if (x[b * 512 + tid] == 0)       ea = -1e10f;
    if (x[b * 512 + tid + 256] == 0) eb = -1e10f;
    red[tid] = fmaxf(ea, eb); __syncthreads();
    for (int s = 128; s > 0; s >>= 1) {
        if (tid < s) red[tid] = fmaxf(red[tid], red[tid + s]);
        __syncthreads();
    }
    float mx = red[0]; __syncthreads();
    float xa = __expf(ea - mx), xb = __expf(eb - mx);
    red[tid] = xa + xb; __syncthreads();
    for (int s = 128; s > 0; s >>= 1) {
        if (tid < s) red[tid] += red[tid + s];
        __syncthreads();
    }
    float inv = __fdividef(1.f, red[0]);
    sa[tid] = xa * inv;
    sa[tid + 256] = xb * inv;
    __syncthreads();

    int d = chunk * 128 + (tid & 127);
    int th = tid >> 7;
    const __half* hp = &g_hs[(size_t)b * 1024 + d];
    float s0 = 0.f, s1 = 0.f;
    #pragma unroll 4
    for (int t = th * 256; t < th * 256 + 256; t += 2) {
        s0 += sa[t]     * __half2float(hp[(size_t)t       * 64 * 1024]);
        s1 += sa[t + 1] * __half2float(hp[(size_t)(t + 1) * 64 * 1024]);
    }
    red[tid] = s0 + s1;
    __syncthreads();
    if (tid < 128) g_ctx[b * HID + d] = red[tid] + red[tid + 128];
}

// ---------------- K7: final classifier (fp32) ----------------
__global__ void final_kernel(const float* __restrict__ WV, const float* __restrict__ bV,
                             float* __restrict__ out) {
    int i = blockIdx.x * blockDim.x + threadIdx.x;
    if (i >= B_ * NCLS) return;
    int b = i / NCLS, n = i % NCLS;
    const float* c = &g_ctx[b * HID];
    const float* w = &WV[n * HID];
    float s = bV[n];
    #pragma unroll 8
    for (int k = 0; k < HID; k++) s += c[k] * w[k];
    out[i] = s;
}

// ---------------- launch ----------------
extern "C" void kernel_launch(void* const* d_in, const int* in_sizes, int n_in,
                              void* d_out, int out_size) {
    const int*   x   = (const int*)  d_in[0];
    const float* emb = (const float*)d_in[1];
    const float* Wg  = (const float*)d_in[2];
    const float* bg  = (const float*)d_in[3];
    const float* Wa  = (const float*)d_in[4];
    const float* va  = (const float*)d_in[5];
    const float* WV  = (const float*)d_in[6];
    const float* bV  = (const float*)d_in[7];
    float* out = (float*)d_out;
    (void)n_in; (void)in_sizes; (void)out_size;

    reset_kernel<<<128, 256>>>();
    convert_kernel<<<2048, 256>>>(Wg, Wa);
    gather_kernel<<<BS_, 256>>>(x, emb);

    const int smem_xc = (128 * ASTRIDE + 2 * BBUF) * (int)sizeof(__half);  // 202752
    cudaFuncSetAttribute(xc_kernel, cudaFuncAttributeMaxDynamicSharedMemorySize, smem_xc);
    xc_kernel<<<dim3(4, 256), 256, smem_xc>>>(bg);

    const int smem_scan = (64 * 1032 + 32 * 1032) * (int)sizeof(__half);   // 198144
    cudaFuncSetAttribute(scan_kernel, cudaFuncAttributeMaxDynamicSharedMemorySize, smem_scan);
    scan_kernel<<<NCTA, 256, smem_scan>>>();

    const int smem_en = (64 * EBSTRIDE + 2 * BBUF) * (int)sizeof(__half);  // 201728
    cudaFuncSetAttribute(energy_kernel, cudaFuncAttributeMaxDynamicSharedMemorySize, smem_en);
    energy_kernel<<<dim3(16, 16), 256, smem_en>>>(va);

    attn_kernel<<<dim3(8, 64), 256>>>(x);
    final_kernel<<<3, 256>>>(WV, bV, out);
}

// round 16
// speedup vs baseline: 1.0435x; 1.0002x over previous
#include <cuda_runtime.h>
#include <cuda_fp16.h>
#include <cstdint>

#define VOCAB 50257
#define EMBED 512
#define HID   1024
#define G4    4096
#define NCLS  10
#define B_    64
#define S_    512
#define BS_   (B_*S_)
#define NCTA  128

// ---------------- device scratch (no allocations allowed) ----------------
__device__ __half  g_E16[(size_t)BS_*EMBED];    // gathered embeddings, row r = t*64+b
__device__ __half  g_Wx16[(size_t)G4*EMBED];    // Wg[:, :512] fp16
__device__ __half  g_Wh16[(size_t)G4*HID];      // Wg[:, 512:] fp16, scan-permuted rows
__device__ __half  g_Wa16[(size_t)HID*HID];
__device__ __half  g_Xc [(size_t)BS_*G4];       // x-part of gates (+bg), blocked cols
__device__ __half  g_hs [(size_t)BS_*HID];      // all hidden states, row r = t*64+b
__device__ float   g_energy[BS_];
__device__ float   g_ctx[B_*HID];
__device__ unsigned g_barc[256];                // [2 groups][4 chunks] x 32-word padding

// ---------------- helpers ----------------
__device__ __forceinline__ void ldmx4(unsigned r[4], const void* p) {
    unsigned a = (unsigned)__cvta_generic_to_shared(p);
    asm volatile("ldmatrix.sync.aligned.m8n8.x4.shared.b16 {%0,%1,%2,%3}, [%4];"
        : "=r"(r[0]), "=r"(r[1]), "=r"(r[2]), "=r"(r[3]) : "r"(a));
}
__device__ __forceinline__ void mma16816(float* c, const unsigned* a, const unsigned* b) {
    asm volatile("mma.sync.aligned.m16n8k16.row.col.f32.f16.f16.f32 "
        "{%0,%1,%2,%3},{%4,%5,%6,%7},{%8,%9},{%0,%1,%2,%3};"
        : "+f"(c[0]), "+f"(c[1]), "+f"(c[2]), "+f"(c[3])
        : "r"(a[0]), "r"(a[1]), "r"(a[2]), "r"(a[3]), "r"(b[0]), "r"(b[1]));
}
__device__ __forceinline__ unsigned ld_acq(const unsigned* p) {
    unsigned v;
    asm volatile("ld.acquire.gpu.global.u32 %0, [%1];" : "=r"(v) : "l"(p) : "memory");
    return v;
}
__device__ __forceinline__ void red_rel_add(unsigned* p, unsigned v) {
    asm volatile("red.release.gpu.global.add.u32 [%0], %1;" :: "l"(p), "r"(v) : "memory");
}
__device__ __forceinline__ void cp16(void* dst, const void* src) {
    unsigned d = (unsigned)__cvta_generic_to_shared(dst);
    asm volatile("cp.async.cg.shared.global [%0], [%1], 16;" :: "r"(d), "l"(src));
}
__device__ __forceinline__ float fsig(float x) { return __fdividef(1.f, 1.f + __expf(-x)); }
__device__ __forceinline__ float ftanh(float x) { return 2.f * fsig(2.f * x) - 1.f; }

// ---------------- K0: reset per-launch state ----------------
__global__ void reset_kernel() {
    int i = blockIdx.x * blockDim.x + threadIdx.x;
    if (i < 256) g_barc[i] = 0u;
    if (i < BS_) g_energy[i] = 0.f;
}

// ---------------- K1: fp32 -> fp16 weight conversions ----------------
__global__ void convert_kernel(const float* __restrict__ Wg, const float* __restrict__ Wa) {
    size_t i0 = (size_t)blockIdx.x * blockDim.x + threadIdx.x;
    size_t stride = (size_t)gridDim.x * blockDim.x;
    for (size_t i = i0; i < (size_t)G4 * EMBED; i += stride) {
        int n = (int)(i >> 9), k = (int)(i & 511);
        g_Wx16[i] = __float2half_rn(Wg[(size_t)n * 1536 + k]);
    }
    // scan layout: row = hc*64 + p, p = d_local*4 + q  <->  original n = q*1024 + hc*16 + d_local
    for (size_t i = i0; i < (size_t)G4 * HID; i += stride) {
        int pos = (int)(i >> 10), k = (int)(i & 1023);
        int hc = pos >> 6, p = pos & 63;
        int n = ((p & 3) << 10) + (hc << 4) + (p >> 2);
        g_Wh16[i] = __float2half_rn(Wg[(size_t)n * 1536 + 512 + k]);
    }
    for (size_t i = i0; i < (size_t)HID * HID; i += stride)
        g_Wa16[i] = __float2half_rn(Wa[i]);
}

// ---------------- K2: gather embeddings to fp16, row = t*64+b ----------------
__global__ void gather_kernel(const int* __restrict__ x, const float* __restrict__ emb) {
    size_t i = (size_t)blockIdx.x * blockDim.x + threadIdx.x;   // over BS_*256 half2
    if (i >= (size_t)BS_ * 256) return;
    int r = (int)(i >> 8), k2 = (int)(i & 255);
    int b = r & 63, t = r >> 6;
    int tok = x[b * 512 + t];
    float2 v = ((const float2*)emb)[(size_t)tok * 256 + k2];
    ((half2*)g_E16)[i] = __floats2half2_rn(v.x, v.y);
}

// ---------------- K3: Xc GEMM v4 — A-tile resident, 8 warps of 64x32 tiles ----------------
// grid (4 bq, 256 bm). A-tile (128 x 512, 133KB) loaded once; loops 8 strips of 128 cols,
// streaming B in 128-K chunks through a 2x34KB double buffer. Warp grid 2(m) x 4(n).
#define ASTRIDE 520
#define BSTRIDE 136
#define BBUF    (128 * BSTRIDE)
__global__ __launch_bounds__(256, 1) void xc_kernel(const float* __restrict__ aux) {
    extern __shared__ __half xs[];
    __half* Asm = xs;                       // 128 x 520
    __half* Bsm = xs + 128 * ASTRIDE;       // 2 x 128 x 136

    int tid = threadIdx.x;
    int warp = tid >> 5, lane = tid & 31;
    int wm = warp >> 2, wn = warp & 3;      // 2x4 warp grid, 64x32 tiles over 128x128
    int grp = lane >> 2, c0 = (lane & 3) * 2;
    int bq = blockIdx.x, bm = blockIdx.y;

    // load A tile: 128 rows x 512 halfs (8192 16B chunks, 32 per thread)
    #pragma unroll
    for (int i = 0; i < 32; i++) {
        int idx = tid + i * 256;
        int r = idx >> 6, s = idx & 63;
        cp16(&Asm[r * ASTRIDE + s * 8], &g_E16[(size_t)(bm * 128 + r) * 512 + s * 8]);
    }
    asm volatile("cp.async.commit_group;");

    auto loadB = [&](int j, int st) {       // j in [0,32): strip (j>>2), K-chunk (j&3)
        int str = j >> 2, c = j & 3;
        #pragma unroll
        for (int i = 0; i < 8; i++) {
            int idx = tid + i * 256;        // 2048 chunks: 128 rows x 16
            int r = idx >> 4, s = idx & 15;
            cp16(&Bsm[st * BBUF + r * BSTRIDE + s * 8],
                 &g_Wx16[(size_t)(bq * 1024 + str * 128 + r) * 512 + c * 128 + s * 8]);
        }
        asm volatile("cp.async.commit_group;");
    };

    float acc[4][4][4];
    #pragma unroll
    for (int a = 0; a < 4; a++)
        #pragma unroll
        for (int b = 0; b < 4; b++)
            #pragma unroll
            for (int c = 0; c < 4; c++) acc[a][b][c] = 0.f;

    loadB(0, 0);
    #pragma unroll 1
    for (int j = 0; j < 32; j++) {
        int c = j & 3;
        if (j < 31) {
            loadB(j + 1, (j + 1) & 1);
            asm volatile("cp.async.wait_group 1;");   // A + chunk j done, j+1 in flight
        } else {
            asm volatile("cp.async.wait_group 0;");
        }
        __syncthreads();
        const __half* bs = &Bsm[(j & 1) * BBUF];
        #pragma unroll
        for (int kk = 0; kk < 128; kk += 16) {
            unsigned af[4][4];
            #pragma unroll
            for (int mf = 0; mf < 4; mf++)
                ldmx4(af[mf], &Asm[(wm * 64 + mf * 16 + (lane & 15)) * ASTRIDE
                                   + c * 128 + kk + ((lane >> 4) << 3)]);
            unsigned bf[4][2];
            #pragma unroll
            for (int hb = 0; hb < 2; hb++) {
                unsigned r[4];
                int n = wn * 32 + hb * 16 + ((lane >> 4) << 3) + (lane & 7);
                int kq = kk + (((lane >> 3) & 1) << 3);
                ldmx4(r, &bs[n * BSTRIDE + kq]);
                bf[hb * 2 + 0][0] = r[0]; bf[hb * 2 + 0][1] = r[1];
                bf[hb * 2 + 1][0] = r[2]; bf[hb * 2 + 1][1] = r[3];
            }
            #pragma unroll
            for (int mf = 0; mf < 4; mf++)
                #pragma unroll
                for (int nf = 0; nf < 4; nf++)
                    mma16816(acc[mf][nf], af[mf], bf[nf]);
        }

        if (c == 3) {                       // finished K for this strip: epilogue + reset
            int str = j >> 2;
            #pragma unroll
            for (int mf = 0; mf < 4; mf++)
                #pragma unroll
                for (int rp = 0; rp < 2; rp++) {
                    int rg = bm * 128 + wm * 64 + mf * 16 + grp + rp * 8;
                    #pragma unroll
                    for (int nf = 0; nf < 4; nf++) {
                        int n0 = bq * 1024 + str * 128 + wn * 32 + nf * 8 + c0;
                        float v0 = acc[mf][nf][rp * 2 + 0] + aux[n0];
                        float v1 = acc[mf][nf][rp * 2 + 1] + aux[n0 + 1];
                        int q = n0 >> 10, d = n0 & 1023;
                        int p = ((d >> 3) << 5) + (q << 3) + (d & 7);
                        *(half2*)&g_Xc[(size_t)rg * G4 + p] = __floats2half2_rn(v0, v1);
                    }
                }
            #pragma unroll
            for (int a = 0; a < 4; a++)
                #pragma unroll
                for (int b = 0; b < 4; b++)
                    #pragma unroll
                    for (int cc = 0; cc < 4; cc++) acc[a][b][cc] = 0.f;
        }
        __syncthreads();                    // buffer j&1 reads done before issue(j+2)
    }
}

// ---------------- K5: energy GEMM v2 — B-tile resident, A streamed ----------------
// grid (16 bn, 16 bmg). B strip (64 n-rows x 1024 K, 132KB) resident; loops 16 bm tiles
// (128 rows), streaming A in 128-K chunks through a 2x34KB double buffer.
// T = hs @ Wa16^T; sum_n tanh(T)*va[n] -> atomicAdd g_energy[row].
#define EBSTRIDE 1032
__global__ __launch_bounds__(256, 1) void energy_kernel(const float* __restrict__ aux) {
    extern __shared__ __half es[];
    __half* Bsm = es;                       // 64 x 1032 (resident)
    __half* Asm = es + 64 * EBSTRIDE;       // 2 x 128 x 136

    int tid = threadIdx.x;
    int warp = tid >> 5, lane = tid & 31;
    int wm = warp & 3, wn = warp >> 2;      // 4x2 warp grid, 32x32 tiles
    int grp = lane >> 2, c0 = (lane & 3) * 2;
    int bn = blockIdx.x, bmg = blockIdx.y;

    #pragma unroll
    for (int i = 0; i < 32; i++) {
        int idx = tid + i * 256;
        int r = idx >> 7, s = idx & 127;
        cp16(&Bsm[r * EBSTRIDE + s * 8], &g_Wa16[(size_t)(bn * 64 + r) * 1024 + s * 8]);
    }
    asm volatile("cp.async.commit_group;");

    auto loadA = [&](int j, int st) {       // j in [0,128): bm tile (j>>3), K-chunk (j&7)
        int bm = bmg * 16 + (j >> 3), c = j & 7;
        #pragma unroll
        for (int i = 0; i < 8; i++) {
            int idx = tid + i * 256;        // 2048 chunks: 128 rows x 16
            int r = idx >> 4, s = idx & 15;
            cp16(&Asm[st * BBUF + r * BSTRIDE + s * 8],
                 &g_hs[(size_t)(bm * 128 + r) * 1024 + c * 128 + s * 8]);
        }
        asm volatile("cp.async.commit_group;");
    };

    float acc[2][4][4];
    #pragma unroll
    for (int a = 0; a < 2; a++)
        #pragma unroll
        for (int b = 0; b < 4; b++)
            #pragma unroll
            for (int c = 0; c < 4; c++) acc[a][b][c] = 0.f;

    loadA(0, 0);
    #pragma unroll 1
    for (int j = 0; j < 128; j++) {
        int c = j & 7;
        if (j < 127) {
            loadA(j + 1, (j + 1) & 1);
            asm volatile("cp.async.wait_group 1;");   // B + chunk j done, j+1 in flight
        } else {
            asm volatile("cp.async.wait_group 0;");
        }
        __syncthreads();
        const __half* as = &Asm[(j & 1) * BBUF];
        #pragma unroll
        for (int kk = 0; kk < 128; kk += 16) {
            unsigned af[2][4];
            #pragma unroll
            for (int mf = 0; mf < 2; mf++)
                ldmx4(af[mf], &as[(wm * 32 + mf * 16 + (lane & 15)) * BSTRIDE
                                  + kk + ((lane >> 4) << 3)]);
            unsigned bf[4][2];
            #pragma unroll
            for (int hb = 0; hb < 2; hb++) {
                unsigned r[4];
                int n = wn * 32 + hb * 16 + ((lane >> 4) << 3) + (lane & 7);
                int kq = c * 128 + kk + (((lane >> 3) & 1) << 3);
                ldmx4(r, &Bsm[n * EBSTRIDE + kq]);
                bf[hb * 2 + 0][0] = r[0]; bf[hb * 2 + 0][1] = r[1];
                bf[hb * 2 + 1][0] = r[2]; bf[hb * 2 + 1][1] = r[3];
            }
            #pragma unroll
            for (int mf = 0; mf < 2; mf++)
                #pragma unroll
                for (int nf = 0; nf < 4; nf++)
                    mma16816(acc[mf][nf], af[mf], bf[nf]);
        }

        if (c == 7) {                       // finished K for this bm tile: epilogue + reset
            int bm = bmg * 16 + (j >> 3);
            #pragma unroll
            for (int mf = 0; mf < 2; mf++)
                #pragma unroll
                for (int rp = 0; rp < 2; rp++) {
                    int rg = bm * 128 + wm * 32 + mf * 16 + grp + rp * 8;
                    float s = 0.f;
                    #pragma unroll
                    for (int nf = 0; nf < 4; nf++)
                        #pragma unroll
                        for (int cc = 0; cc < 2; cc++) {
                            int n = bn * 64 + wn * 32 + nf * 8 + c0 + cc;
                            s += ftanh(acc[mf][nf][rp * 2 + cc]) * aux[n];
                        }
                    s += __shfl_xor_sync(0xffffffffu, s, 1);
                    s += __shfl_xor_sync(0xffffffffu, s, 2);
                    if ((lane & 3) == 0) atomicAdd(&g_energy[rg], s);
                }
            #pragma unroll
            for (int a = 0; a < 2; a++)
                #pragma unroll
                for (int b = 0; b < 4; b++)
                    #pragma unroll
                    for (int cc = 0; cc < 4; cc++) acc[a][b][cc] = 0.f;
        }
        __syncthreads();                    // buffer j&1 reads done before issue(j+2)
    }
}

// ---------------- K4: persistent LSTM scan v6.1 — per-K-chunk barriers, all-lane poll ----------------
// CTA (bg,hc): batch rows [bg*32,+32), dims [hc*16,+16) -> 64 gate cols (p = d*4+q).
// 8 warps: (wk) K-chunk of 256, (wn) 32 gate cols. Weight fragments in registers.
// Chunk wk of h_{t-1} is produced by the 16 CTAs with hc>>4==wk -> warp-pair wk waits
// ONLY on barrier slot (bg,wk). ALL 64 lanes poll (own acquire orders own cp.async).
__global__ __launch_bounds__(256, 1) void scan_kernel() {
    extern __shared__ __half sh[];
    __half* Wsm = sh;                              // 64 x 1032 (dead after preload)
    __half* Hsm = sh + 64 * 1032;                  // 32 x 1032
    float*  Psf = (float*)sh;                      // alias into Wsm: [4][32][68] fp32
    int tid = threadIdx.x, cta = blockIdx.x;
    int w = tid >> 5, lane = tid & 31;
    int wk = w >> 1, wn = w & 1;
    int grp = lane >> 2, c0 = (lane & 3) * 2;
    int bg = cta >> 6, hc = cta & 63;
    int kbase = wk * 256;
    int lt = tid & 63;                             // lane within warp pair
    unsigned* wait_slot = &g_barc[(bg * 4 + wk) * 32];          // consumer side
    unsigned* arr_slot  = &g_barc[(bg * 4 + (hc >> 4)) * 32];   // producer side

    // stage weights: rows hc*64 .. hc*64+64 of scan-permuted Wh
    for (int i = tid; i < 64 * 128; i += 256) {
        int r = i >> 7, s = i & 127;
        *(uint4*)&Wsm[r * 1032 + s * 8] =
            *(const uint4*)&g_Wh16[((size_t)hc * 64 + r) * 1024 + s * 8];
    }
    __syncthreads();

    // preload this warp's weight fragments for its whole 256-K chunk into registers
    unsigned bfr[16][4][2];
    {
        int n = wn * 32 + ((lane >> 4) << 3) + (lane & 7);
        #pragma unroll
        for (int it = 0; it < 16; it++) {
            int kq = kbase + it * 16 + (((lane >> 3) & 1) << 3);
            unsigned r[4];
            ldmx4(r, &Wsm[n * 1032 + kq]);
            bfr[it][0][0] = r[0]; bfr[it][0][1] = r[1];
            bfr[it][1][0] = r[2]; bfr[it][1][1] = r[3];
            ldmx4(r, &Wsm[(n + 16) * 1032 + kq]);
            bfr[it][2][0] = r[0]; bfr[it][2][1] = r[1];
            bfr[it][3][0] = r[2]; bfr[it][3][1] = r[3];
        }
    }
    __syncthreads();   // Wsm reads complete before Psf (alias) is ever written

    int m = tid >> 3, e0 = (tid & 7) * 2;          // epilogue ownership: row m, dims e0,e0+1
    int rowg = bg * 32 + m;
    int xbase = (((hc * 16 + e0) >> 3) << 5) + (e0 & 7);   // blocked Xc addressing
    float cc0 = 0.f, cc1 = 0.f;

    for (int t = 0; t < S_; t++) {
        // prefetch x-part of gates (independent of h_{t-1})
        const __half* xrow = &g_Xc[((size_t)t * 64 + rowg) * G4 + xbase];
        half2 hx0 = *(const half2*)&xrow[0];
        half2 hx1 = *(const half2*)&xrow[8];
        half2 hx2 = *(const half2*)&xrow[16];
        half2 hx3 = *(const half2*)&xrow[24];

        float acc[2][4][4];
        #pragma unroll
        for (int a = 0; a < 2; a++)
            #pragma unroll
            for (int b = 0; b < 4; b++)
                #pragma unroll
                for (int c = 0; c < 4; c++) acc[a][b][c] = 0.f;

        if (t > 0) {
            // per-chunk wait: EVERY lane polls; its own acquire orders its own cp.async
            {
                unsigned target = 16u * (unsigned)t;
                while (ld_acq(wait_slot) < target) {}
            }

            // warp pair stages 32 rows x 256 K in TWO 8KB halves (overlap load 2 w/ mma 1)
            const __half* hp = &g_hs[((size_t)(t - 1) * 64 + bg * 32) * 1024];
            #pragma unroll
            for (int i = 0; i < 8; i++) {
                int idx = lt + i * 64;             // 0..511: 32 rows x 16 chunks
                int r = idx >> 4, s = idx & 15;
                cp16(&Hsm[r * 1032 + kbase + s * 8], &hp[r * 1024 + kbase + s * 8]);
            }
            asm volatile("cp.async.commit_group;");
            #pragma unroll
            for (int i = 0; i < 8; i++) {
                int idx = lt + i * 64;
                int r = idx >> 4, s = idx & 15;
                cp16(&Hsm[r * 1032 + kbase + 128 + s * 8], &hp[r * 1024 + kbase + 128 + s * 8]);
            }
            asm volatile("cp.async.commit_group;");

            #pragma unroll
            for (int half = 0; half < 2; half++) {
                if (half == 0) asm volatile("cp.async.wait_group 1;");
                else           asm volatile("cp.async.wait_group 0;");
                asm volatile("bar.sync %0, 64;" :: "r"(1 + wk));
                #pragma unroll
                for (int it = half * 8; it < half * 8 + 8; it++) {
                    int kk = kbase + it * 16;
                    unsigned af[2][4];
                    #pragma unroll
                    for (int mf = 0; mf < 2; mf++)
                        ldmx4(af[mf], &Hsm[(mf * 16 + (lane & 15)) * 1032 + kk + ((lane >> 4) << 3)]);
                    #pragma unroll
                    for (int mf = 0; mf < 2; mf++)
                        #pragma unroll
                        for (int nf = 0; nf < 4; nf++)
                            mma16816(acc[mf][nf], af[mf], bfr[it][nf]);
                }
            }
        }

        // Psum write (aliases Wsm, NOT Hsm; prev-step Psf reads finished at loop-end sync)
        #pragma unroll
        for (int mf = 0; mf < 2; mf++)
            #pragma unroll
            for (int nf = 0; nf < 4; nf++)
                #pragma unroll
                for (int rp = 0; rp < 2; rp++) {
                    int mm = mf * 16 + grp + rp * 8;
                    *(float2*)&Psf[(wk * 32 + mm) * 68 + wn * 32 + nf * 8 + c0] =
                        make_float2(acc[mf][nf][rp * 2 + 0], acc[mf][nf][rp * 2 + 1]);
                }
        __syncthreads();

        // cell update: this thread owns (row m, dims e0,e0+1); Psum cols p = e*4+q
        float4 sa = make_float4(0.f, 0.f, 0.f, 0.f);
        float4 sb = make_float4(0.f, 0.f, 0.f, 0.f);
        #pragma unroll
        for (int k = 0; k < 4; k++) {
            float4 va = *(const float4*)&Psf[(k * 32 + m) * 68 + e0 * 4];
            float4 vb = *(const float4*)&Psf[(k * 32 + m) * 68 + e0 * 4 + 4];
            sa.x += va.x; sa.y += va.y; sa.z += va.z; sa.w += va.w;
            sb.x += vb.x; sb.y += vb.y; sb.z += vb.z; sb.w += vb.w;
        }
        float h0, h1;
        {
            float iv = fsig (sa.x + __low2float(hx0));
            float fv = fsig (sa.y + __low2float(hx1));
            float gv = ftanh(sa.z + __low2float(hx2));
            float ov = fsig (sa.w + __low2float(hx3));
            cc0 = fv * cc0 + iv * gv;
            h0 = ov * ftanh(cc0);
        }
        {
            float iv = fsig (sb.x + __high2float(hx0));
            float fv = fsig (sb.y + __high2float(hx1));
            float gv = ftanh(sb.z + __high2float(hx2));
            float ov = fsig (sb.w + __high2float(hx3));
            cc1 = fv * cc1 + iv * gv;
            h1 = ov * ftanh(cc1);
        }
        *(half2*)&g_hs[((size_t)t * 64 + rowg) * 1024 + hc * 16 + e0] =
            __floats2half2_rn(h0, h1);

        __syncthreads();                 // all h STG + Psf reads done before release
        if (tid == 0) red_rel_add(arr_slot, 1u);
    }
}

// ---------------- K6: masked softmax + context, grid (8 dim-chunks, 64 batch) ----------------
__global__ void attn_kernel(const int* __restrict__ x) {
    __shared__ float sa[512];
    __shared__ float red[256];
    int chunk = blockIdx.x, b = blockIdx.y, tid = threadIdx.x;

    float ea = g_energy[tid * 64 + b];
    float eb = g_energy[(tid + 256) * 64 + b];
    if (x[b * 512 + tid] == 0)       ea = -1e10f;
    if (x[b * 512 + tid + 256] == 0) eb = -1e10f;
    red[tid] = fmaxf(ea, eb); __syncthreads();
    for (int s = 128; s > 0; s >>= 1) {
        if (tid < s) red[tid] = fmaxf(red[tid], red[tid + s]);
        __syncthreads();
    }
    float mx = red[0]; __syncthreads();
    float xa = __expf(ea - mx), xb = __expf(eb - mx);
    red[tid] = xa + xb; __syncthreads();
    for (int s = 128; s > 0; s >>= 1) {
        if (tid < s) red[tid] += red[tid + s];
        __syncthreads();
    }
    float inv = __fdividef(1.f, red[0]);
    sa[tid] = xa * inv;
    sa[tid + 256] = xb * inv;
    __syncthreads();

    int d = chunk * 128 + (tid & 127);
    int th = tid >> 7;
    const __half* hp = &g_hs[(size_t)b * 1024 + d];
    float s0 = 0.f, s1 = 0.f;
    #pragma unroll 4
    for (int t = th * 256; t < th * 256 + 256; t += 2) {
        s0 += sa[t]     * __half2float(hp[(size_t)t       * 64 * 1024]);
        s1 += sa[t + 1] * __half2float(hp[(size_t)(t + 1) * 64 * 1024]);
    }
    red[tid] = s0 + s1;
    __syncthreads();
    if (tid < 128) g_ctx[b * HID + d] = red[tid] + red[tid + 128];
}

// ---------------- K7: final classifier (fp32) ----------------
__global__ void final_kernel(const float* __restrict__ WV, const float* __restrict__ bV,
                             float* __restrict__ out) {
    int i = blockIdx.x * blockDim.x + threadIdx.x;
    if (i >= B_ * NCLS) return;
    int b = i / NCLS, n = i % NCLS;
    const float* c = &g_ctx[b * HID];
    const float* w = &WV[n * HID];
    float s = bV[n];
    #pragma unroll 8
    for (int k = 0; k < HID; k++) s += c[k] * w[k];
    out[i] = s;
}

// ---------------- launch ----------------
extern "C" void kernel_launch(void* const* d_in, const int* in_sizes, int n_in,
                              void* d_out, int out_size) {
    const int*   x   = (const int*)  d_in[0];
    const float* emb = (const float*)d_in[1];
    const float* Wg  = (const float*)d_in[2];
    const float* bg  = (const float*)d_in[3];
    const float* Wa  = (const float*)d_in[4];
    const float* va  = (const float*)d_in[5];
    const float* WV  = (const float*)d_in[6];
    const float* bV  = (const float*)d_in[7];
    float* out = (float*)d_out;
    (void)n_in; (void)in_sizes; (void)out_size;

    reset_kernel<<<128, 256>>>();
    convert_kernel<<<2048, 256>>>(Wg, Wa);
    gather_kernel<<<BS_, 256>>>(x, emb);

    const int smem_xc = (128 * ASTRIDE + 2 * BBUF) * (int)sizeof(__half);  // 202752
    cudaFuncSetAttribute(xc_kernel, cudaFuncAttributeMaxDynamicSharedMemorySize, smem_xc);
    xc_kernel<<<dim3(4, 256), 256, smem_xc>>>(bg);

    const int smem_scan = (64 * 1032 + 32 * 1032) * (int)sizeof(__half);   // 198144
    cudaFuncSetAttribute(scan_kernel, cudaFuncAttributeMaxDynamicSharedMemorySize, smem_scan);
    scan_kernel<<<NCTA, 256, smem_scan>>>();

    const int smem_en = (64 * EBSTRIDE + 2 * BBUF) * (int)sizeof(__half);  // 201728
    cudaFuncSetAttribute(energy_kernel, cudaFuncAttributeMaxDynamicSharedMemorySize, smem_en);
    energy_kernel<<<dim3(16, 16), 256, smem_en>>>(va);

    attn_kernel<<<dim3(8, 64), 256>>>(x);
    final_kernel<<<3, 256>>>(WV, bV, out);
}

// round 17
// speedup vs baseline: 1.0963x; 1.0506x over previous
#include <cuda_runtime.h>
#include <cuda_fp16.h>
#include <cstdint>

#define VOCAB 50257
#define EMBED 512
#define HID   1024
#define G4    4096
#define NCLS  10
#define B_    64
#define S_    512
#define BS_   (B_*S_)
#define NCTA  128

// ---------------- device scratch (no allocations allowed) ----------------
__device__ __half  g_E16[(size_t)BS_*EMBED];    // gathered embeddings, row r = t*64+b
__device__ __half  g_Wx16[(size_t)G4*EMBED];    // Wg[:, :512] fp16
__device__ __half  g_Wh16[(size_t)G4*HID];      // Wg[:, 512:] fp16, scan-permuted rows
__device__ __half  g_Wa16[(size_t)HID*HID];
__device__ __half  g_Xc [(size_t)BS_*G4];       // x-part of gates (+bg), blocked cols
__device__ __half  g_hs [(size_t)BS_*HID];      // all hidden states, row r = t*64+b
__device__ float   g_energy[BS_];
__device__ float   g_ctx[B_*HID];
__device__ unsigned g_barc[256];                // [2 groups][4 chunks] x 32-word padding

// ---------------- helpers ----------------
__device__ __forceinline__ void ldmx4(unsigned r[4], const void* p) {
    unsigned a = (unsigned)__cvta_generic_to_shared(p);
    asm volatile("ldmatrix.sync.aligned.m8n8.x4.shared.b16 {%0,%1,%2,%3}, [%4];"
        : "=r"(r[0]), "=r"(r[1]), "=r"(r[2]), "=r"(r[3]) : "r"(a));
}
__device__ __forceinline__ void mma16816(float* c, const unsigned* a, const unsigned* b) {
    asm volatile("mma.sync.aligned.m16n8k16.row.col.f32.f16.f16.f32 "
        "{%0,%1,%2,%3},{%4,%5,%6,%7},{%8,%9},{%0,%1,%2,%3};"
        : "+f"(c[0]), "+f"(c[1]), "+f"(c[2]), "+f"(c[3])
        : "r"(a[0]), "r"(a[1]), "r"(a[2]), "r"(a[3]), "r"(b[0]), "r"(b[1]));
}
__device__ __forceinline__ unsigned ld_acq(const unsigned* p) {
    unsigned v;
    asm volatile("ld.acquire.gpu.global.u32 %0, [%1];" : "=r"(v) : "l"(p) : "memory");
    return v;
}
__device__ __forceinline__ void red_rel_add(unsigned* p, unsigned v) {
    asm volatile("red.release.gpu.global.add.u32 [%0], %1;" :: "l"(p), "r"(v) : "memory");
}
__device__ __forceinline__ void cp16(void* dst, const void* src) {
    unsigned d = (unsigned)__cvta_generic_to_shared(dst);
    asm volatile("cp.async.cg.shared.global [%0], [%1], 16;" :: "r"(d), "l"(src));
}
__device__ __forceinline__ float fsig(float x) { return __fdividef(1.f, 1.f + __expf(-x)); }
__device__ __forceinline__ float ftanh(float x) { return 2.f * fsig(2.f * x) - 1.f; }

// ---------------- K0: reset per-launch state ----------------
__global__ void reset_kernel() {
    int i = blockIdx.x * blockDim.x + threadIdx.x;
    if (i < 256) g_barc[i] = 0u;
    if (i < BS_) g_energy[i] = 0.f;
}

// ---------------- K1: fp32 -> fp16 weight conversions ----------------
__global__ void convert_kernel(const float* __restrict__ Wg, const float* __restrict__ Wa) {
    size_t i0 = (size_t)blockIdx.x * blockDim.x + threadIdx.x;
    size_t stride = (size_t)gridDim.x * blockDim.x;
    for (size_t i = i0; i < (size_t)G4 * EMBED; i += stride) {
        int n = (int)(i >> 9), k = (int)(i & 511);
        g_Wx16[i] = __float2half_rn(Wg[(size_t)n * 1536 + k]);
    }
    // scan layout: row = hc*64 + p, p = d_local*4 + q  <->  original n = q*1024 + hc*16 + d_local
    for (size_t i = i0; i < (size_t)G4 * HID; i += stride) {
        int pos = (int)(i >> 10), k = (int)(i & 1023);
        int hc = pos >> 6, p = pos & 63;
        int n = ((p & 3) << 10) + (hc << 4) + (p >> 2);
        g_Wh16[i] = __float2half_rn(Wg[(size_t)n * 1536 + 512 + k]);
    }
    for (size_t i = i0; i < (size_t)HID * HID; i += stride)
        g_Wa16[i] = __float2half_rn(Wa[i]);
}

// ---------------- K2: gather embeddings to fp16, row = t*64+b ----------------
__global__ void gather_kernel(const int* __restrict__ x, const float* __restrict__ emb) {
    size_t i = (size_t)blockIdx.x * blockDim.x + threadIdx.x;   // over BS_*256 half2
    if (i >= (size_t)BS_ * 256) return;
    int r = (int)(i >> 8), k2 = (int)(i & 255);
    int b = r & 63, t = r >> 6;
    int tok = x[b * 512 + t];
    float2 v = ((const float2*)emb)[(size_t)tok * 256 + k2];
    ((half2*)g_E16)[i] = __floats2half2_rn(v.x, v.y);
}

// ---------------- K3: Xc GEMM v4 — A-tile resident, 8 warps of 64x32 tiles ----------------
#define ASTRIDE 520
#define BSTRIDE 136
#define BBUF    (128 * BSTRIDE)
__global__ __launch_bounds__(256, 1) void xc_kernel(const float* __restrict__ aux) {
    extern __shared__ __half xs[];
    __half* Asm = xs;                       // 128 x 520
    __half* Bsm = xs + 128 * ASTRIDE;       // 2 x 128 x 136

    int tid = threadIdx.x;
    int warp = tid >> 5, lane = tid & 31;
    int wm = warp >> 2, wn = warp & 3;      // 2x4 warp grid, 64x32 tiles over 128x128
    int grp = lane >> 2, c0 = (lane & 3) * 2;
    int bq = blockIdx.x, bm = blockIdx.y;

    #pragma unroll
    for (int i = 0; i < 32; i++) {
        int idx = tid + i * 256;
        int r = idx >> 6, s = idx & 63;
        cp16(&Asm[r * ASTRIDE + s * 8], &g_E16[(size_t)(bm * 128 + r) * 512 + s * 8]);
    }
    asm volatile("cp.async.commit_group;");

    auto loadB = [&](int j, int st) {       // j in [0,32): strip (j>>2), K-chunk (j&3)
        int str = j >> 2, c = j & 3;
        #pragma unroll
        for (int i = 0; i < 8; i++) {
            int idx = tid + i * 256;        // 2048 chunks: 128 rows x 16
            int r = idx >> 4, s = idx & 15;
            cp16(&Bsm[st * BBUF + r * BSTRIDE + s * 8],
                 &g_Wx16[(size_t)(bq * 1024 + str * 128 + r) * 512 + c * 128 + s * 8]);
        }
        asm volatile("cp.async.commit_group;");
    };

    float acc[4][4][4];
    #pragma unroll
    for (int a = 0; a < 4; a++)
        #pragma unroll
        for (int b = 0; b < 4; b++)
            #pragma unroll
            for (int c = 0; c < 4; c++) acc[a][b][c] = 0.f;

    loadB(0, 0);
    #pragma unroll 1
    for (int j = 0; j < 32; j++) {
        int c = j & 3;
        if (j < 31) {
            loadB(j + 1, (j + 1) & 1);
            asm volatile("cp.async.wait_group 1;");
        } else {
            asm volatile("cp.async.wait_group 0;");
        }
        __syncthreads();
        const __half* bs = &Bsm[(j & 1) * BBUF];
        #pragma unroll
        for (int kk = 0; kk < 128; kk += 16) {
            unsigned af[4][4];
            #pragma unroll
            for (int mf = 0; mf < 4; mf++)
                ldmx4(af[mf], &Asm[(wm * 64 + mf * 16 + (lane & 15)) * ASTRIDE
                                   + c * 128 + kk + ((lane >> 4) << 3)]);
            unsigned bf[4][2];
            #pragma unroll
            for (int hb = 0; hb < 2; hb++) {
                unsigned r[4];
                int n = wn * 32 + hb * 16 + ((lane >> 4) << 3) + (lane & 7);
                int kq = kk + (((lane >> 3) & 1) << 3);
                ldmx4(r, &bs[n * BSTRIDE + kq]);
                bf[hb * 2 + 0][0] = r[0]; bf[hb * 2 + 0][1] = r[1];
                bf[hb * 2 + 1][0] = r[2]; bf[hb * 2 + 1][1] = r[3];
            }
            #pragma unroll
            for (int mf = 0; mf < 4; mf++)
                #pragma unroll
                for (int nf = 0; nf < 4; nf++)
                    mma16816(acc[mf][nf], af[mf], bf[nf]);
        }

        if (c == 3) {
            int str = j >> 2;
            #pragma unroll
            for (int mf = 0; mf < 4; mf++)
                #pragma unroll
                for (int rp = 0; rp < 2; rp++) {
                    int rg = bm * 128 + wm * 64 + mf * 16 + grp + rp * 8;
                    #pragma unroll
                    for (int nf = 0; nf < 4; nf++) {
                        int n0 = bq * 1024 + str * 128 + wn * 32 + nf * 8 + c0;
                        float v0 = acc[mf][nf][rp * 2 + 0] + aux[n0];
                        float v1 = acc[mf][nf][rp * 2 + 1] + aux[n0 + 1];
                        int q = n0 >> 10, d = n0 & 1023;
                        int p = ((d >> 3) << 5) + (q << 3) + (d & 7);
                        *(half2*)&g_Xc[(size_t)rg * G4 + p] = __floats2half2_rn(v0, v1);
                    }
                }
            #pragma unroll
            for (int a = 0; a < 4; a++)
                #pragma unroll
                for (int b = 0; b < 4; b++)
                    #pragma unroll
                    for (int cc = 0; cc < 4; cc++) acc[a][b][cc] = 0.f;
        }
        __syncthreads();
    }
}

// ---------------- K4: FUSED persistent scan (CTAs 0..127) + gated energy GEMM (CTAs 128..383) ----
// Scan: v6.1 per-K-chunk barriers, all-lane poll, register-resident weights.
// Energy: B-resident GEMM; each 128-row bm tile (timesteps 2bm,2bm+1) gated on the scan's
// progress counters (all 8 slots >= 16*(2bm+2)) via tid0 acquire-poll + __syncthreads.
#define EBSTRIDE 1032
__global__ __launch_bounds__(256, 1) void scan_energy_kernel(const float* __restrict__ va) {
    extern __shared__ char fsm[];
    int tid = threadIdx.x;

    if (blockIdx.x < 128) {
        // ================= SCAN (identical body to R16) =================
        __half* Wsm = (__half*)fsm;                    // 64 x 1032 (dead after preload)
        __half* Hsm = (__half*)fsm + 64 * 1032;        // 32 x 1032
        float*  Psf = (float*)fsm;                     // alias into Wsm: [4][32][68] fp32
        int cta = blockIdx.x;
        int w = tid >> 5, lane = tid & 31;
        int wk = w >> 1, wn = w & 1;
        int grp = lane >> 2, c0 = (lane & 3) * 2;
        int bg = cta >> 6, hc = cta & 63;
        int kbase = wk * 256;
        int lt = tid & 63;
        unsigned* wait_slot = &g_barc[(bg * 4 + wk) * 32];
        unsigned* arr_slot  = &g_barc[(bg * 4 + (hc >> 4)) * 32];

        for (int i = tid; i < 64 * 128; i += 256) {
            int r = i >> 7, s = i & 127;
            *(uint4*)&Wsm[r * 1032 + s * 8] =
                *(const uint4*)&g_Wh16[((size_t)hc * 64 + r) * 1024 + s * 8];
        }
        __syncthreads();

        unsigned bfr[16][4][2];
        {
            int n = wn * 32 + ((lane >> 4) << 3) + (lane & 7);
            #pragma unroll
            for (int it = 0; it < 16; it++) {
                int kq = kbase + it * 16 + (((lane >> 3) & 1) << 3);
                unsigned r[4];
                ldmx4(r, &Wsm[n * 1032 + kq]);
                bfr[it][0][0] = r[0]; bfr[it][0][1] = r[1];
                bfr[it][1][0] = r[2]; bfr[it][1][1] = r[3];
                ldmx4(r, &Wsm[(n + 16) * 1032 + kq]);
                bfr[it][2][0] = r[0]; bfr[it][2][1] = r[1];
                bfr[it][3][0] = r[2]; bfr[it][3][1] = r[3];
            }
        }
        __syncthreads();

        int m = tid >> 3, e0 = (tid & 7) * 2;
        int rowg = bg * 32 + m;
        int xbase = (((hc * 16 + e0) >> 3) << 5) + (e0 & 7);
        float cc0 = 0.f, cc1 = 0.f;

        for (int t = 0; t < S_; t++) {
            const __half* xrow = &g_Xc[((size_t)t * 64 + rowg) * G4 + xbase];
            half2 hx0 = *(const half2*)&xrow[0];
            half2 hx1 = *(const half2*)&xrow[8];
            half2 hx2 = *(const half2*)&xrow[16];
            half2 hx3 = *(const half2*)&xrow[24];

            float acc[2][4][4];
            #pragma unroll
            for (int a = 0; a < 2; a++)
                #pragma unroll
                for (int b = 0; b < 4; b++)
                    #pragma unroll
                    for (int c = 0; c < 4; c++) acc[a][b][c] = 0.f;

            if (t > 0) {
                {
                    unsigned target = 16u * (unsigned)t;
                    while (ld_acq(wait_slot) < target) {}
                }
                const __half* hp = &g_hs[((size_t)(t - 1) * 64 + bg * 32) * 1024];
                #pragma unroll
                for (int i = 0; i < 8; i++) {
                    int idx = lt + i * 64;
                    int r = idx >> 4, s = idx & 15;
                    cp16(&Hsm[r * 1032 + kbase + s * 8], &hp[r * 1024 + kbase + s * 8]);
                }
                asm volatile("cp.async.commit_group;");
                #pragma unroll
                for (int i = 0; i < 8; i++) {
                    int idx = lt + i * 64;
                    int r = idx >> 4, s = idx & 15;
                    cp16(&Hsm[r * 1032 + kbase + 128 + s * 8], &hp[r * 1024 + kbase + 128 + s * 8]);
                }
                asm volatile("cp.async.commit_group;");

                #pragma unroll
                for (int half = 0; half < 2; half++) {
                    if (half == 0) asm volatile("cp.async.wait_group 1;");
                    else           asm volatile("cp.async.wait_group 0;");
                    asm volatile("bar.sync %0, 64;" :: "r"(1 + wk));
                    #pragma unroll
                    for (int it = half * 8; it < half * 8 + 8; it++) {
                        int kk = kbase + it * 16;
                        unsigned af[2][4];
                        #pragma unroll
                        for (int mf = 0; mf < 2; mf++)
                            ldmx4(af[mf], &Hsm[(mf * 16 + (lane & 15)) * 1032 + kk + ((lane >> 4) << 3)]);
                        #pragma unroll
                        for (int mf = 0; mf < 2; mf++)
                            #pragma unroll
                            for (int nf = 0; nf < 4; nf++)
                                mma16816(acc[mf][nf], af[mf], bfr[it][nf]);
                    }
                }
            }

            #pragma unroll
            for (int mf = 0; mf < 2; mf++)
                #pragma unroll
                for (int nf = 0; nf < 4; nf++)
                    #pragma unroll
                    for (int rp = 0; rp < 2; rp++) {
                        int mm = mf * 16 + grp + rp * 8;
                        *(float2*)&Psf[(wk * 32 + mm) * 68 + wn * 32 + nf * 8 + c0] =
                            make_float2(acc[mf][nf][rp * 2 + 0], acc[mf][nf][rp * 2 + 1]);
                    }
            __syncthreads();

            float4 sa = make_float4(0.f, 0.f, 0.f, 0.f);
            float4 sb = make_float4(0.f, 0.f, 0.f, 0.f);
            #pragma unroll
            for (int k = 0; k < 4; k++) {
                float4 vva = *(const float4*)&Psf[(k * 32 + m) * 68 + e0 * 4];
                float4 vvb = *(const float4*)&Psf[(k * 32 + m) * 68 + e0 * 4 + 4];
                sa.x += vva.x; sa.y += vva.y; sa.z += vva.z; sa.w += vva.w;
                sb.x += vvb.x; sb.y += vvb.y; sb.z += vvb.z; sb.w += vvb.w;
            }
            float h0, h1;
            {
                float iv = fsig (sa.x + __low2float(hx0));
                float fv = fsig (sa.y + __low2float(hx1));
                float gv = ftanh(sa.z + __low2float(hx2));
                float ov = fsig (sa.w + __low2float(hx3));
                cc0 = fv * cc0 + iv * gv;
                h0 = ov * ftanh(cc0);
            }
            {
                float iv = fsig (sb.x + __high2float(hx0));
                float fv = fsig (sb.y + __high2float(hx1));
                float gv = ftanh(sb.z + __high2float(hx2));
                float ov = fsig (sb.w + __high2float(hx3));
                cc1 = fv * cc1 + iv * gv;
                h1 = ov * ftanh(cc1);
            }
            *(half2*)&g_hs[((size_t)t * 64 + rowg) * 1024 + hc * 16 + e0] =
                __floats2half2_rn(h0, h1);

            __syncthreads();
            if (tid == 0) red_rel_add(arr_slot, 1u);
        }
    } else {
        // ================= ENERGY (gated on scan progress) =================
        __half* Bsm = (__half*)fsm;                    // 64 x 1032 (resident)
        __half* Asm = (__half*)fsm + 64 * EBSTRIDE;    // 2 x 128 x 136
        __shared__ unsigned s_go;

        int blk = blockIdx.x - 128;
        int bn = blk & 15, bmg = blk >> 4;
        int warp = tid >> 5, lane = tid & 31;
        int wm = warp & 3, wn = warp >> 2;             // 4x2 warp grid, 32x32 tiles
        int grp = lane >> 2, c0 = (lane & 3) * 2;

        #pragma unroll
        for (int i = 0; i < 32; i++) {
            int idx = tid + i * 256;
            int r = idx >> 7, s = idx & 127;
            cp16(&Bsm[r * EBSTRIDE + s * 8], &g_Wa16[(size_t)(bn * 64 + r) * 1024 + s * 8]);
        }
        asm volatile("cp.async.commit_group;");

        auto gate = [&](int bm) {                      // wait hs rows < (2bm+2)*64 published
            if (tid == 0) {
                unsigned need = 16u * (unsigned)(2 * bm + 2);
                for (;;) {
                    bool ok = true;
                    #pragma unroll
                    for (int s = 0; s < 8; s++)
                        if (ld_acq(&g_barc[s * 32]) < need) { ok = false; break; }
                    if (ok) break;
                    __nanosleep(200);
                }
                s_go = 1u;
            }
            __syncthreads();
        };

        auto loadA = [&](int j, int st) {              // j in [0,128): bm tile (j>>3), chunk (j&7)
            int bm = bmg * 16 + (j >> 3), c = j & 7;
            #pragma unroll
            for (int i = 0; i < 8; i++) {
                int idx = tid + i * 256;
                int r = idx >> 4, s = idx & 15;
                cp16(&Asm[st * BBUF + r * BSTRIDE + s * 8],
                     &g_hs[(size_t)(bm * 128 + r) * 1024 + c * 128 + s * 8]);
            }
            asm volatile("cp.async.commit_group;");
        };

        float acc[2][4][4];
        #pragma unroll
        for (int a = 0; a < 2; a++)
            #pragma unroll
            for (int b = 0; b < 4; b++)
                #pragma unroll
                for (int c = 0; c < 4; c++) acc[a][b][c] = 0.f;

        gate(bmg * 16);
        loadA(0, 0);
        #pragma unroll 1
        for (int j = 0; j < 128; j++) {
            int c = j & 7;
            if (j < 127) {
                if (((j + 1) & 7) == 0) gate(bmg * 16 + ((j + 1) >> 3));
                loadA(j + 1, (j + 1) & 1);
                asm volatile("cp.async.wait_group 1;");
            } else {
                asm volatile("cp.async.wait_group 0;");
            }
            __syncthreads();
            const __half* as = &Asm[(j & 1) * BBUF];
            #pragma unroll
            for (int kk = 0; kk < 128; kk += 16) {
                unsigned af[2][4];
                #pragma unroll
                for (int mf = 0; mf < 2; mf++)
                    ldmx4(af[mf], &as[(wm * 32 + mf * 16 + (lane & 15)) * BSTRIDE
                                      + kk + ((lane >> 4) << 3)]);
                unsigned bf[4][2];
                #pragma unroll
                for (int hb = 0; hb < 2; hb++) {
                    unsigned r[4];
                    int n = wn * 32 + hb * 16 + ((lane >> 4) << 3) + (lane & 7);
                    int kq = c * 128 + kk + (((lane >> 3) & 1) << 3);
                    ldmx4(r, &Bsm[n * EBSTRIDE + kq]);
                    bf[hb * 2 + 0][0] = r[0]; bf[hb * 2 + 0][1] = r[1];
                    bf[hb * 2 + 1][0] = r[2]; bf[hb * 2 + 1][1] = r[3];
                }
                #pragma unroll
                for (int mf = 0; mf < 2; mf++)
                    #pragma unroll
                    for (int nf = 0; nf < 4; nf++)
                        mma16816(acc[mf][nf], af[mf], bf[nf]);
            }

            if (c == 7) {
                int bm = bmg * 16 + (j >> 3);
                #pragma unroll
                for (int mf = 0; mf < 2; mf++)
                    #pragma unroll
                    for (int rp = 0; rp < 2; rp++) {
                        int rg = bm * 128 + wm * 32 + mf * 16 + grp + rp * 8;
                        float s = 0.f;
                        #pragma unroll
                        for (int nf = 0; nf < 4; nf++)
                            #pragma unroll
                            for (int cc2 = 0; cc2 < 2; cc2++) {
                                int n = bn * 64 + wn * 32 + nf * 8 + c0 + cc2;
                                s += ftanh(acc[mf][nf][rp * 2 + cc2]) * va[n];
                            }
                        s += __shfl_xor_sync(0xffffffffu, s, 1);
                        s += __shfl_xor_sync(0xffffffffu, s, 2);
                        if ((lane & 3) == 0) atomicAdd(&g_energy[rg], s);
                    }
                #pragma unroll
                for (int a = 0; a < 2; a++)
                    #pragma unroll
                    for (int b = 0; b < 4; b++)
                        #pragma unroll
                        for (int cc2 = 0; cc2 < 4; cc2++) acc[a][b][cc2] = 0.f;
            }
            __syncthreads();
        }
    }
}

// ---------------- K6: masked softmax + context, grid (8 dim-chunks, 64 batch) ----------------
__global__ void attn_kernel(const int* __restrict__ x) {
    __shared__ float sa[512];
    __shared__ float red[256];
    int chunk = blockIdx.x, b = blockIdx.y, tid = threadIdx.x;

    float ea = g_energy[tid * 64 + b];
    float eb = g_energy[(tid + 256) * 64 + b];
    if (x[b * 512 + tid] == 0)       ea = -1e10f;
    if (x[b * 512 + tid + 256] == 0) eb = -1e10f;
    red[tid] = fmaxf(ea, eb); __syncthreads();
    for (int s = 128; s > 0; s >>= 1) {
        if (tid < s) red[tid] = fmaxf(red[tid], red[tid + s]);
        __syncthreads();
    }
    float mx = red[0]; __syncthreads();
    float xa = __expf(ea - mx), xb = __expf(eb - mx);
    red[tid] = xa + xb; __syncthreads();
    for (int s = 128; s > 0; s >>= 1) {
        if (tid < s) red[tid] += red[tid + s];
        __syncthreads();
    }
    float inv = __fdividef(1.f, red[0]);
    sa[tid] = xa * inv;
    sa[tid + 256] = xb * inv;
    __syncthreads();

    int d = chunk * 128 + (tid & 127);
    int th = tid >> 7;
    const __half* hp = &g_hs[(size_t)b * 1024 + d];
    float s0 = 0.f, s1 = 0.f;
    #pragma unroll 4
    for (int t = th * 256; t < th * 256 + 256; t += 2) {
        s0 += sa[t]     * __half2float(hp[(size_t)t       * 64 * 1024]);
        s1 += sa[t + 1] * __half2float(hp[(size_t)(t + 1) * 64 * 1024]);
    }
    red[tid] = s0 + s1;
    __syncthreads();
    if (tid < 128) g_ctx[b * HID + d] = red[tid] + red[tid + 128];
}

// ---------------- K7: final classifier (fp32) ----------------
__global__ void final_kernel(const float* __restrict__ WV, const float* __restrict__ bV,
                             float* __restrict__ out) {
    int i = blockIdx.x * blockDim.x + threadIdx.x;
    if (i >= B_ * NCLS) return;
    int b = i / NCLS, n = i % NCLS;
    const float* c = &g_ctx[b * HID];
    const float* w = &WV[n * HID];
    float s = bV[n];
    #pragma unroll 8
    for (int k = 0; k < HID; k++) s += c[k] * w[k];
    out[i] = s;
}

// ---------------- launch ----------------
extern "C" void kernel_launch(void* const* d_in, const int* in_sizes, int n_in,
                              void* d_out, int out_size) {
    const int*   x   = (const int*)  d_in[0];
    const float* emb = (const float*)d_in[1];
    const float* Wg  = (const float*)d_in[2];
    const float* bg  = (const float*)d_in[3];
    const float* Wa  = (const float*)d_in[4];
    const float* va  = (const float*)d_in[5];
    const float* WV  = (const float*)d_in[6];
    const float* bV  = (const float*)d_in[7];
    float* out = (float*)d_out;
    (void)n_in; (void)in_sizes; (void)out_size;

    reset_kernel<<<128, 256>>>();
    convert_kernel<<<2048, 256>>>(Wg, Wa);
    gather_kernel<<<BS_, 256>>>(x, emb);

    const int smem_xc = (128 * ASTRIDE + 2 * BBUF) * (int)sizeof(__half);  // 202752
    cudaFuncSetAttribute(xc_kernel, cudaFuncAttributeMaxDynamicSharedMemorySize, smem_xc);
    xc_kernel<<<dim3(4, 256), 256, smem_xc>>>(bg);

    const int smem_fused = (64 * EBSTRIDE + 2 * BBUF) * (int)sizeof(__half);  // 201728 >= scan's 198144
    cudaFuncSetAttribute(scan_energy_kernel, cudaFuncAttributeMaxDynamicSharedMemorySize, smem_fused);
    scan_energy_kernel<<<128 + 256, 256, smem_fused>>>(va);

    attn_kernel<<<dim3(8, 64), 256>>>(x);
    final_kernel<<<3, 256>>>(WV, bV, out);
}